// round 4
// baseline (speedup 1.0000x reference)
#include <cuda_runtime.h>
#include <math.h>

#define HH 64
#define WWD 192
#define HWX (HH*WWD)       // 12288
#define HP 66
#define WP 194
#define PP (HP*WP)         // 12804
#define CIN 256
#define CO 128
#define BM 32
#define BN 128
#define BK 16
#define NBLK (HWX/BM)      // 384 gemm row-blocks

typedef unsigned long long u64x;

__device__ __forceinline__ u64x pack2(float x, float y) {
    u64x r;
    asm("mov.b64 %0, {%1, %2};" : "=l"(r) : "f"(x), "f"(y));
    return r;
}
__device__ __forceinline__ u64x ffma2(u64x a, u64x b, u64x c) {
    u64x d;
    asm("fma.rn.f32x2 %0, %1, %2, %3;" : "=l"(d) : "l"(a), "l"(b), "l"(c));
    return d;
}
__device__ __forceinline__ void unpack2(u64x v, float& lo, float& hi) {
    asm("mov.b64 {%0, %1}, %2;" : "=f"(lo), "=f"(hi) : "l"(v));
}

// ---------------- scratch (device globals; no allocation) ----------------
__device__ float g_xT[PP*CIN];      // padded x, pixel-major (P, Cin)
__device__ int   g_gn[HWX];         // compact entry count per pixel
__device__ int   g_gi[HWX*40];      // idx | (tap<<16)
__device__ float g_gw[HWX*40];      // merged weights
__device__ float g_yT[HWX*CIN];     // gather output, pixel-major
__device__ float g_C1[HWX*CO];
__device__ float g_Z1[HWX*CO];
__device__ float g_C2[HWX*CO];
__device__ float g_Z2[HWX*CO];
__device__ float g_C3[HWX*CO];
__device__ float g_psum[NBLK*CO];
__device__ float g_psq[NBLK*CO];
__device__ float g_bn[3*2*CO];      // per stage: [scale(128), shift(128)]

// ---------------- 1) pad + transpose x: (Cin,H,W) -> (P, Cin) ----------------
__global__ void k_pad_transpose(const float* __restrict__ x) {
    __shared__ float s[32][33];
    int ptile = blockIdx.x * 32;
    int ctile = blockIdx.y * 32;
    int tx = threadIdx.x, ty = threadIdx.y;   // 32 x 8
    #pragma unroll
    for (int i = 0; i < 32; i += 8) {
        int c = ctile + ty + i;
        int p = ptile + tx;
        float v = 0.f;
        if (p < PP) {
            int ph = p / WP, pw = p % WP;
            if (ph >= 1 && ph <= HH && pw >= 1 && pw <= WWD)
                v = x[c*HWX + (ph-1)*WWD + (pw-1)];
        }
        s[ty+i][tx] = v;
    }
    __syncthreads();
    #pragma unroll
    for (int i = 0; i < 32; i += 8) {
        int p = ptile + ty + i;
        if (p < PP) g_xT[p*CIN + ctile + tx] = s[tx][ty+i];
    }
}

// ---------------- 2) per-pixel compact (idx,weight,tap) list ----------------
__global__ void k_weights(const float* __restrict__ x_range) {
    int p = blockIdx.x * blockDim.x + threadIdx.x;
    if (p >= HWX) return;
    int h = p / WWD, w = p % WWD;
    float off = 3.0f / (1.0f + expf(-x_range[p]));
    float v0 = (float)((h+1)*WP + (w+1));
    const float PM1 = (float)(PP - 1);
    int   li[40];
    float lw[40];
    int cnt = 0;
    #pragma unroll
    for (int t = 0; t < 9; t++) {
        float xo = (float)(t % 3 - 1);
        float yo = (float)(t / 3 - 1);
        float pre   = v0 + xo + yo*(float)WP;
        float ofv   = off*xo + yo*(float)WP;
        float after = pre + ofv;
        float avf  = fminf(fmaxf(pre + floorf(ofv), 0.f), PM1);
        float avf1 = fminf(fmaxf(avf + xo, 0.f), PM1);
        float avc  = fminf(fmaxf(pre + ceilf(ofv), 0.f), PM1);
        float avc1 = fminf(fmaxf(avc + xo, 0.f), PM1);
        float s1 = fabsf((after - avf)  / (float)WP);
        float s2 = fabsf((avc1 - after) / (float)WP);
        int   id4[4];
        float w4[4];
        id4[0] = (int)avf;  w4[0] = s1 * fabsf(after - avf);
        id4[1] = (int)avf1; w4[1] = s1 * fabsf(avf1 - after);
        id4[2] = (int)avc1; w4[2] = s2 * fabsf(after - avc1);
        id4[3] = (int)avc;  w4[3] = s2 * fabsf(avc - after);
        int start = cnt;
        #pragma unroll
        for (int j = 0; j < 4; j++) {
            if (w4[j] == 0.f) continue;
            bool merged = false;
            for (int e = start; e < cnt; e++) {
                if (li[e] == (id4[j] | (t << 16))) { lw[e] += w4[j]; merged = true; break; }
            }
            if (!merged) { li[cnt] = id4[j] | (t << 16); lw[cnt] = w4[j]; cnt++; }
        }
    }
    g_gn[p] = cnt;
    for (int e = 0; e < cnt; e++) {
        g_gi[p*40 + e] = li[e];
        g_gw[p*40 + e] = lw[e];
    }
}

// ---------------- 3) gather + tap-reduce -> yT (HW, Cin), float4 channels ----------------
__global__ void k_gather(const float* __restrict__ range_out) {
    __shared__ float rcs[CIN*9];       // 9216 B
    __shared__ int   si[4][40];
    __shared__ float sw[4][40];
    __shared__ int   scnt[4];
    int tid = threadIdx.x;             // 256
    int sub = tid >> 6;                // pixel within block (0..3)
    int c4  = tid & 63;                // channel group (4 ch each)
    int p = blockIdx.x * 4 + sub;
    for (int i = tid; i < CIN*9; i += 256) rcs[i] = range_out[i];
    if (c4 == 0) scnt[sub] = g_gn[p];
    if (c4 < 40) { si[sub][c4] = g_gi[p*40 + c4]; sw[sub][c4] = g_gw[p*40 + c4]; }
    __syncthreads();
    int cnt = scnt[sub];
    int cb = c4 * 4;
    float4 rc[9];
    #pragma unroll
    for (int t = 0; t < 9; t++)
        rc[t] = make_float4(rcs[(cb+0)*9+t], rcs[(cb+1)*9+t], rcs[(cb+2)*9+t], rcs[(cb+3)*9+t]);
    float4 acc = make_float4(0.f,0.f,0.f,0.f);
    float4 sb  = make_float4(0.f,0.f,0.f,0.f);
    int curt = -1;
    for (int e = 0; e < cnt; e++) {
        int ent = si[sub][e];
        int idx = ent & 0xFFFF;
        int t   = ent >> 16;
        if (t != curt) {
            if (curt >= 0) {
                acc.x += rc[curt].x*sb.x; acc.y += rc[curt].y*sb.y;
                acc.z += rc[curt].z*sb.z; acc.w += rc[curt].w*sb.w;
            }
            sb = make_float4(0.f,0.f,0.f,0.f);
            curt = t;
        }
        float wv = sw[sub][e];
        float4 v = *(const float4*)&g_xT[idx*CIN + cb];
        sb.x += wv*v.x; sb.y += wv*v.y; sb.z += wv*v.z; sb.w += wv*v.w;
    }
    if (curt >= 0) {
        acc.x += rc[curt].x*sb.x; acc.y += rc[curt].y*sb.y;
        acc.z += rc[curt].z*sb.z; acc.w += rc[curt].w*sb.w;
    }
    *(float4*)&g_yT[p*CIN + cb] = acc;
}

// ---------------- 4) NT GEMM with packed FFMA2, + BN partials ----------------
// C[p][o] = sum_k A[p][k]*B[o][k].  BM=32, BN=128, BK=16, 128 threads, 4x8 microtile.
__global__ __launch_bounds__(128) void k_gemm(const float* __restrict__ A,
                                              const float* __restrict__ B,
                                              float* __restrict__ C, int K) {
    __shared__ float As[BK][BM+4];
    __shared__ float Bs[BK][BN+4];
    __shared__ float reds[8][BN];
    __shared__ float redq[8][BN];
    int t = threadIdx.x;
    int m0 = blockIdx.x * BM;
    int ntx = t & 15;        // col group: 8 cols
    int mty = t >> 4;        // row group: 4 rows
    int ar = t >> 2;         // A load: row 0..31
    int ak = (t & 3) * 4;    // A load: k offset 0,4,8,12
    const float* Aptr = A + (m0 + ar)*K + ak;
    const float* Bptr = B + t*K;

    u64x acc[4][4];
    #pragma unroll
    for (int i = 0; i < 4; i++)
        #pragma unroll
        for (int j = 0; j < 4; j++) acc[i][j] = 0ull;

    float4 aP, bP0, bP1, bP2, bP3;
    aP  = *(const float4*)(Aptr);
    bP0 = *(const float4*)(Bptr + 0);
    bP1 = *(const float4*)(Bptr + 4);
    bP2 = *(const float4*)(Bptr + 8);
    bP3 = *(const float4*)(Bptr + 12);

    int ktiles = K / BK;
    for (int kt = 0; kt < ktiles; kt++) {
        As[ak+0][ar] = aP.x; As[ak+1][ar] = aP.y; As[ak+2][ar] = aP.z; As[ak+3][ar] = aP.w;
        Bs[ 0][t] = bP0.x; Bs[ 1][t] = bP0.y; Bs[ 2][t] = bP0.z; Bs[ 3][t] = bP0.w;
        Bs[ 4][t] = bP1.x; Bs[ 5][t] = bP1.y; Bs[ 6][t] = bP1.z; Bs[ 7][t] = bP1.w;
        Bs[ 8][t] = bP2.x; Bs[ 9][t] = bP2.y; Bs[10][t] = bP2.z; Bs[11][t] = bP2.w;
        Bs[12][t] = bP3.x; Bs[13][t] = bP3.y; Bs[14][t] = bP3.z; Bs[15][t] = bP3.w;
        __syncthreads();
        if (kt + 1 < ktiles) {
            int ko = (kt + 1) * BK;
            aP  = *(const float4*)(Aptr + ko);
            bP0 = *(const float4*)(Bptr + ko + 0);
            bP1 = *(const float4*)(Bptr + ko + 4);
            bP2 = *(const float4*)(Bptr + ko + 8);
            bP3 = *(const float4*)(Bptr + ko + 12);
        }
        #pragma unroll
        for (int k = 0; k < BK; k++) {
            float4 av = *(const float4*)&As[k][mty*4];
            ulonglong2 bl = *(const ulonglong2*)&Bs[k][ntx*8];
            ulonglong2 bh = *(const ulonglong2*)&Bs[k][ntx*8 + 4];
            float a4[4] = {av.x, av.y, av.z, av.w};
            #pragma unroll
            for (int i = 0; i < 4; i++) {
                u64x ap = pack2(a4[i], a4[i]);
                acc[i][0] = ffma2(ap, bl.x, acc[i][0]);
                acc[i][1] = ffma2(ap, bl.y, acc[i][1]);
                acc[i][2] = ffma2(ap, bh.x, acc[i][2]);
                acc[i][3] = ffma2(ap, bh.y, acc[i][3]);
            }
        }
        __syncthreads();
    }

    // epilogue: write C + deterministic BN partial sums
    float s[8], q[8];
    #pragma unroll
    for (int j = 0; j < 8; j++) { s[j] = 0.f; q[j] = 0.f; }
    #pragma unroll
    for (int i = 0; i < 4; i++) {
        float cv[8];
        #pragma unroll
        for (int jp = 0; jp < 4; jp++) unpack2(acc[i][jp], cv[2*jp], cv[2*jp+1]);
        float* crow = &C[(m0 + mty*4 + i)*CO + ntx*8];
        *(float4*)(crow)     = make_float4(cv[0], cv[1], cv[2], cv[3]);
        *(float4*)(crow + 4) = make_float4(cv[4], cv[5], cv[6], cv[7]);
        #pragma unroll
        for (int j = 0; j < 8; j++) { s[j] += cv[j]; q[j] += cv[j]*cv[j]; }
    }
    #pragma unroll
    for (int j = 0; j < 8; j++) { reds[mty][ntx*8+j] = s[j]; redq[mty][ntx*8+j] = q[j]; }
    __syncthreads();
    if (t < BN) {
        float ts = 0.f, tq = 0.f;
        #pragma unroll
        for (int g = 0; g < 8; g++) { ts += reds[g][t]; tq += redq[g][t]; }
        g_psum[blockIdx.x*CO + t] = ts;
        g_psq [blockIdx.x*CO + t] = tq;
    }
}

// ---------------- 5) BN finalize: one block per channel, tree reduce ----------------
__global__ void k_bn_final(const float* __restrict__ gg, const float* __restrict__ bb, int stage) {
    __shared__ float ss[128], sq[128];
    int o = blockIdx.x;       // channel
    int t = threadIdx.x;      // 128
    float s = 0.f, q = 0.f;
    for (int i = t; i < NBLK; i += 128) { s += g_psum[i*CO + o]; q += g_psq[i*CO + o]; }
    ss[t] = s; sq[t] = q;
    __syncthreads();
    for (int st = 64; st > 0; st >>= 1) {
        if (t < st) { ss[t] += ss[t+st]; sq[t] += sq[t+st]; }
        __syncthreads();
    }
    if (t == 0) {
        float inv = 1.0f / (float)HWX;
        float mu  = ss[0] * inv;
        float var = sq[0] * inv - mu*mu;
        float sc  = gg[o] * rsqrtf(var + 1e-5f);
        g_bn[stage*2*CO + o]      = sc;
        g_bn[stage*2*CO + CO + o] = bb[o] - mu*sc;
    }
}

// ---------------- 6) depthwise 3x3 on act(C), float4 channels, 8 px/block ----------------
__global__ void k_dw(const float* __restrict__ Cin_, const float* __restrict__ dww,
                     float* __restrict__ Z, int stage) {
    __shared__ float dws[CO*9];
    int tid = threadIdx.x;          // 256
    int pg = tid >> 5;              // 0..7 pixel in block
    int cg = tid & 31;              // 0..31 channel group (4 ch)
    for (int i = tid; i < CO*9; i += 256) dws[i] = dww[i];
    __syncthreads();
    int p = blockIdx.x * 8 + pg;
    int h = p / WWD, w = p % WWD;
    int cb = cg * 4;
    float4 sc = *(const float4*)&g_bn[stage*2*CO + cb];
    float4 sh = *(const float4*)&g_bn[stage*2*CO + CO + cb];
    float4 acc = make_float4(0.f,0.f,0.f,0.f);
    #pragma unroll
    for (int t = 0; t < 9; t++) {
        int hh = h + t/3 - 1, ww = w + t%3 - 1;
        if (hh < 0 || hh >= HH || ww < 0 || ww >= WWD) continue;
        float4 v = *(const float4*)&Cin_[(hh*WWD + ww)*CO + cb];
        float ax = v.x*sc.x + sh.x; ax = (ax >= 0.f) ? ax : 0.01f*ax;
        float ay = v.y*sc.y + sh.y; ay = (ay >= 0.f) ? ay : 0.01f*ay;
        float az = v.z*sc.z + sh.z; az = (az >= 0.f) ? az : 0.01f*az;
        float aw = v.w*sc.w + sh.w; aw = (aw >= 0.f) ? aw : 0.01f*aw;
        acc.x += dws[(cb+0)*9+t] * ax;
        acc.y += dws[(cb+1)*9+t] * ay;
        acc.z += dws[(cb+2)*9+t] * az;
        acc.w += dws[(cb+3)*9+t] * aw;
    }
    *(float4*)&Z[p*CO + cb] = acc;
}

// ---------------- 7) final act + transpose to NCHW ----------------
__global__ void k_final(float* __restrict__ out) {
    __shared__ float s[32][33];
    int ptile = blockIdx.x * 32;
    int ctile = blockIdx.y * 32;
    int tx = threadIdx.x, ty = threadIdx.y;  // 32 x 8
    #pragma unroll
    for (int i = 0; i < 32; i += 8) {
        int p = ptile + ty + i, c = ctile + tx;
        float v = g_C3[p*CO + c];
        float a = v*g_bn[2*2*CO + c] + g_bn[2*2*CO + CO + c];
        a = (a >= 0.f) ? a : 0.01f*a;
        s[ty+i][tx] = a;
    }
    __syncthreads();
    #pragma unroll
    for (int i = 0; i < 32; i += 8)
        out[(ctile + ty + i)*HWX + ptile + tx] = s[tx][ty+i];
}

// ---------------- launch ----------------
extern "C" void kernel_launch(void* const* d_in, const int* in_sizes, int n_in,
                              void* d_out, int out_size) {
    const float* x        = (const float*)d_in[0];
    const float* x_range  = (const float*)d_in[1];
    const float* range_o  = (const float*)d_in[2];
    const float* w_reduce = (const float*)d_in[3];
    const float* g_r      = (const float*)d_in[4];
    const float* b_r      = (const float*)d_in[5];
    const float* dw1      = (const float*)d_in[6];
    const float* pw1      = (const float*)d_in[7];
    const float* g1       = (const float*)d_in[8];
    const float* b1       = (const float*)d_in[9];
    const float* dw2      = (const float*)d_in[10];
    const float* pw2      = (const float*)d_in[11];
    const float* g2       = (const float*)d_in[12];
    const float* b2       = (const float*)d_in[13];
    float* out = (float*)d_out;

    float *yT, *C1, *Z1, *C2, *Z2, *C3;
    cudaGetSymbolAddress((void**)&yT, g_yT);
    cudaGetSymbolAddress((void**)&C1, g_C1);
    cudaGetSymbolAddress((void**)&Z1, g_Z1);
    cudaGetSymbolAddress((void**)&C2, g_C2);
    cudaGetSymbolAddress((void**)&Z2, g_Z2);
    cudaGetSymbolAddress((void**)&C3, g_C3);

    k_pad_transpose<<<dim3((PP+31)/32, CIN/32), dim3(32,8)>>>(x);
    k_weights<<<(HWX+255)/256, 256>>>(x_range);
    k_gather<<<HWX/4, 256>>>(range_o);

    k_gemm<<<NBLK, 128>>>(yT, w_reduce, C1, CIN);
    k_bn_final<<<CO, 128>>>(g_r, b_r, 0);
    k_dw<<<HWX/8, 256>>>(C1, dw1, Z1, 0);

    k_gemm<<<NBLK, 128>>>(Z1, pw1, C2, CO);
    k_bn_final<<<CO, 128>>>(g1, b1, 1);
    k_dw<<<HWX/8, 256>>>(C2, dw2, Z2, 1);

    k_gemm<<<NBLK, 128>>>(Z2, pw2, C3, CO);
    k_bn_final<<<CO, 128>>>(g2, b2, 2);

    k_final<<<dim3(HWX/32, CO/32), dim3(32,8)>>>(out);
}

// round 8
// speedup vs baseline: 1.0394x; 1.0394x over previous
#include <cuda_runtime.h>
#include <math.h>

#define HH 64
#define WWD 192
#define HWX (HH*WWD)       // 12288
#define HP 66
#define WP 194
#define PP (HP*WP)         // 12804
#define CIN 256
#define CO 128
#define BM 32
#define BN 128
#define BK 16
#define NBLK (HWX/BM)      // 384 gemm row-blocks

typedef unsigned long long u64x;

__device__ __forceinline__ u64x pack2(float x, float y) {
    u64x r;
    asm("mov.b64 %0, {%1, %2};" : "=l"(r) : "f"(x), "f"(y));
    return r;
}
__device__ __forceinline__ u64x ffma2(u64x a, u64x b, u64x c) {
    u64x d;
    asm("fma.rn.f32x2 %0, %1, %2, %3;" : "=l"(d) : "l"(a), "l"(b), "l"(c));
    return d;
}
__device__ __forceinline__ void unpack2(u64x v, float& lo, float& hi) {
    asm("mov.b64 {%0, %1}, %2;" : "=f"(lo), "=f"(hi) : "l"(v));
}

// ---------------- scratch (device globals; no allocation) ----------------
__device__ float g_xT[PP*CIN];      // padded x, pixel-major (P, Cin)
__device__ int   g_gn[HWX];         // compact entry count per pixel
__device__ int   g_gi[HWX*40];      // idx | (tap<<16)
__device__ float g_gw[HWX*40];      // merged weights
__device__ float g_yT[HWX*CIN];     // gather output, pixel-major
__device__ float g_C1[HWX*CO];
__device__ float g_Z1[HWX*CO];
__device__ float g_C2[HWX*CO];
__device__ float g_Z2[HWX*CO];
__device__ float g_C3[HWX*CO];
__device__ float g_psum[NBLK*CO];
__device__ float g_psq[NBLK*CO];
__device__ float g_bn[3*2*CO];      // per stage: [scale(128), shift(128)]

// ---------------- 1) pad + transpose x: (Cin,H,W) -> (P, Cin) ----------------
__global__ void k_pad_transpose(const float* __restrict__ x) {
    __shared__ float s[32][33];
    int ptile = blockIdx.x * 32;
    int ctile = blockIdx.y * 32;
    int tx = threadIdx.x, ty = threadIdx.y;   // 32 x 8
    #pragma unroll
    for (int i = 0; i < 32; i += 8) {
        int c = ctile + ty + i;
        int p = ptile + tx;
        float v = 0.f;
        if (p < PP) {
            int ph = p / WP, pw = p % WP;
            if (ph >= 1 && ph <= HH && pw >= 1 && pw <= WWD)
                v = x[c*HWX + (ph-1)*WWD + (pw-1)];
        }
        s[ty+i][tx] = v;
    }
    __syncthreads();
    #pragma unroll
    for (int i = 0; i < 32; i += 8) {
        int p = ptile + ty + i;
        if (p < PP) g_xT[p*CIN + ctile + tx] = s[tx][ty+i];
    }
}

// ---------------- 2) per-pixel compact (idx,weight,tap) list ----------------
__global__ void k_weights(const float* __restrict__ x_range) {
    int p = blockIdx.x * blockDim.x + threadIdx.x;
    if (p >= HWX) return;
    int h = p / WWD, w = p % WWD;
    float off = 3.0f / (1.0f + expf(-x_range[p]));
    float v0 = (float)((h+1)*WP + (w+1));
    const float PM1 = (float)(PP - 1);
    int   li[40];
    float lw[40];
    int cnt = 0;
    #pragma unroll
    for (int t = 0; t < 9; t++) {
        float xo = (float)(t % 3 - 1);
        float yo = (float)(t / 3 - 1);
        float pre   = v0 + xo + yo*(float)WP;
        float ofv   = off*xo + yo*(float)WP;
        float after = pre + ofv;
        float avf  = fminf(fmaxf(pre + floorf(ofv), 0.f), PM1);
        float avf1 = fminf(fmaxf(avf + xo, 0.f), PM1);
        float avc  = fminf(fmaxf(pre + ceilf(ofv), 0.f), PM1);
        float avc1 = fminf(fmaxf(avc + xo, 0.f), PM1);
        float s1 = fabsf((after - avf)  / (float)WP);
        float s2 = fabsf((avc1 - after) / (float)WP);
        int   id4[4];
        float w4[4];
        id4[0] = (int)avf;  w4[0] = s1 * fabsf(after - avf);
        id4[1] = (int)avf1; w4[1] = s1 * fabsf(avf1 - after);
        id4[2] = (int)avc1; w4[2] = s2 * fabsf(after - avc1);
        id4[3] = (int)avc;  w4[3] = s2 * fabsf(avc - after);
        int start = cnt;
        #pragma unroll
        for (int j = 0; j < 4; j++) {
            if (w4[j] == 0.f) continue;
            bool merged = false;
            for (int e = start; e < cnt; e++) {
                if (li[e] == (id4[j] | (t << 16))) { lw[e] += w4[j]; merged = true; break; }
            }
            if (!merged) { li[cnt] = id4[j] | (t << 16); lw[cnt] = w4[j]; cnt++; }
        }
    }
    g_gn[p] = cnt;
    for (int e = 0; e < cnt; e++) {
        g_gi[p*40 + e] = li[e];
        g_gw[p*40 + e] = lw[e];
    }
}

// ---------------- 3) gather + tap-reduce -> yT (HW, Cin), float4 channels ----------------
__global__ void k_gather(const float* __restrict__ range_out) {
    __shared__ float rcs[CIN*9];       // 9216 B
    __shared__ int   si[4][40];
    __shared__ float sw[4][40];
    __shared__ int   scnt[4];
    int tid = threadIdx.x;             // 256
    int sub = tid >> 6;                // pixel within block (0..3)
    int c4  = tid & 63;                // channel group (4 ch each)
    int p = blockIdx.x * 4 + sub;
    for (int i = tid; i < CIN*9; i += 256) rcs[i] = range_out[i];
    if (c4 == 0) scnt[sub] = g_gn[p];
    if (c4 < 40) { si[sub][c4] = g_gi[p*40 + c4]; sw[sub][c4] = g_gw[p*40 + c4]; }
    __syncthreads();
    int cnt = scnt[sub];
    int cb = c4 * 4;
    float4 rc[9];
    #pragma unroll
    for (int t = 0; t < 9; t++)
        rc[t] = make_float4(rcs[(cb+0)*9+t], rcs[(cb+1)*9+t], rcs[(cb+2)*9+t], rcs[(cb+3)*9+t]);
    float4 acc = make_float4(0.f,0.f,0.f,0.f);
    float4 sb  = make_float4(0.f,0.f,0.f,0.f);
    int curt = -1;
    for (int e = 0; e < cnt; e++) {
        int ent = si[sub][e];
        int idx = ent & 0xFFFF;
        int t   = ent >> 16;
        if (t != curt) {
            if (curt >= 0) {
                acc.x += rc[curt].x*sb.x; acc.y += rc[curt].y*sb.y;
                acc.z += rc[curt].z*sb.z; acc.w += rc[curt].w*sb.w;
            }
            sb = make_float4(0.f,0.f,0.f,0.f);
            curt = t;
        }
        float wv = sw[sub][e];
        float4 v = *(const float4*)&g_xT[idx*CIN + cb];
        sb.x += wv*v.x; sb.y += wv*v.y; sb.z += wv*v.z; sb.w += wv*v.w;
    }
    if (curt >= 0) {
        acc.x += rc[curt].x*sb.x; acc.y += rc[curt].y*sb.y;
        acc.z += rc[curt].z*sb.z; acc.w += rc[curt].w*sb.w;
    }
    *(float4*)&g_yT[p*CIN + cb] = acc;
}

// ---------------- 4) NT GEMM: broadcast-A + FFMA2-along-M, + BN partials ----------------
// C[p][o] = sum_k A[p][k]*B[o][k].  BM=32, BN=128, BK=16, 256 threads, 4x4 microtile.
// Warp-uniform A rows (mty = tid>>5) -> broadcast LDS. B reads 16B/lane -> conflict-free.
__global__ __launch_bounds__(256) void k_gemm(const float* __restrict__ A,
                                              const float* __restrict__ B,
                                              float* __restrict__ C, int K) {
    __shared__ float As[BK][BM];       // reads are warp-broadcast: no padding needed
    __shared__ float Bs[BK][BN+4];     // stride 132 floats = 528B (16B-aligned rows)
    __shared__ float reds[8][BN];
    __shared__ float redq[8][BN];
    int t = threadIdx.x;               // 256
    int m0 = blockIdx.x * BM;
    int mty = t >> 5;                  // 0..7: warp id == row group (warp-uniform A!)
    int ntx = t & 31;                  // 0..31: col group (4 cols)

    // A tile load mapping: r = t&31 (lane), kk2 = t>>5 -> k pair {2*kk2, 2*kk2+1}
    int ar = t & 31;
    int akk = (t >> 5) * 2;
    const float* Aptr = A + (m0 + ar)*K + akk;
    // B tile load mapping: n = t&127, kb = (t>>7)*8 -> 8 k's
    int bn_ = t & 127;
    int bkb = (t >> 7) * 8;
    const float* Bptr = B + bn_*K + bkb;

    u64x acc[2][4];                    // [row-pair][col], row pair p covers rows 2p,2p+1
    #pragma unroll
    for (int i = 0; i < 2; i++)
        #pragma unroll
        for (int j = 0; j < 4; j++) acc[i][j] = 0ull;

    float2 aP = *(const float2*)(Aptr);
    float4 bP0 = *(const float4*)(Bptr);
    float4 bP1 = *(const float4*)(Bptr + 4);

    int ktiles = K / BK;
    for (int kt = 0; kt < ktiles; kt++) {
        // stores: all lane-stride-1, conflict-free
        As[akk+0][ar] = aP.x;
        As[akk+1][ar] = aP.y;
        Bs[bkb+0][bn_] = bP0.x; Bs[bkb+1][bn_] = bP0.y;
        Bs[bkb+2][bn_] = bP0.z; Bs[bkb+3][bn_] = bP0.w;
        Bs[bkb+4][bn_] = bP1.x; Bs[bkb+5][bn_] = bP1.y;
        Bs[bkb+6][bn_] = bP1.z; Bs[bkb+7][bn_] = bP1.w;
        __syncthreads();
        if (kt + 1 < ktiles) {
            int ko = (kt + 1) * BK;
            aP  = *(const float2*)(Aptr + ko);
            bP0 = *(const float4*)(Bptr + ko);
            bP1 = *(const float4*)(Bptr + ko + 4);
        }
        #pragma unroll
        for (int k = 0; k < BK; k++) {
            // broadcast: all lanes in warp read same 16B
            float4 av = *(const float4*)&As[k][mty*4];
            u64x a01 = pack2(av.x, av.y);
            u64x a23 = pack2(av.z, av.w);
            // conflict-free: lane-stride 16B
            float4 bv = *(const float4*)&Bs[k][ntx*4];
            u64x b0 = pack2(bv.x, bv.x);
            u64x b1 = pack2(bv.y, bv.y);
            u64x b2 = pack2(bv.z, bv.z);
            u64x b3 = pack2(bv.w, bv.w);
            acc[0][0] = ffma2(a01, b0, acc[0][0]);
            acc[0][1] = ffma2(a01, b1, acc[0][1]);
            acc[0][2] = ffma2(a01, b2, acc[0][2]);
            acc[0][3] = ffma2(a01, b3, acc[0][3]);
            acc[1][0] = ffma2(a23, b0, acc[1][0]);
            acc[1][1] = ffma2(a23, b1, acc[1][1]);
            acc[1][2] = ffma2(a23, b2, acc[1][2]);
            acc[1][3] = ffma2(a23, b3, acc[1][3]);
        }
        __syncthreads();
    }

    // epilogue: unpack 4 rows x 4 cols, write C + deterministic BN partials
    float cv[4][4];
    #pragma unroll
    for (int pr = 0; pr < 2; pr++)
        #pragma unroll
        for (int j = 0; j < 4; j++)
            unpack2(acc[pr][j], cv[2*pr][j], cv[2*pr+1][j]);

    float s[4], q[4];
    #pragma unroll
    for (int j = 0; j < 4; j++) { s[j] = 0.f; q[j] = 0.f; }
    #pragma unroll
    for (int i = 0; i < 4; i++) {
        *(float4*)&C[(m0 + mty*4 + i)*CO + ntx*4] =
            make_float4(cv[i][0], cv[i][1], cv[i][2], cv[i][3]);
        #pragma unroll
        for (int j = 0; j < 4; j++) { s[j] += cv[i][j]; q[j] += cv[i][j]*cv[i][j]; }
    }
    #pragma unroll
    for (int j = 0; j < 4; j++) { reds[mty][ntx*4+j] = s[j]; redq[mty][ntx*4+j] = q[j]; }
    __syncthreads();
    if (t < BN) {
        float ts = 0.f, tq = 0.f;
        #pragma unroll
        for (int g = 0; g < 8; g++) { ts += reds[g][t]; tq += redq[g][t]; }
        g_psum[blockIdx.x*CO + t] = ts;
        g_psq [blockIdx.x*CO + t] = tq;
    }
}

// ---------------- 5) BN finalize: one block per channel, tree reduce ----------------
__global__ void k_bn_final(const float* __restrict__ gg, const float* __restrict__ bb, int stage) {
    __shared__ float ss[128], sq[128];
    int o = blockIdx.x;       // channel
    int t = threadIdx.x;      // 128
    float s = 0.f, q = 0.f;
    for (int i = t; i < NBLK; i += 128) { s += g_psum[i*CO + o]; q += g_psq[i*CO + o]; }
    ss[t] = s; sq[t] = q;
    __syncthreads();
    for (int st = 64; st > 0; st >>= 1) {
        if (t < st) { ss[t] += ss[t+st]; sq[t] += sq[t+st]; }
        __syncthreads();
    }
    if (t == 0) {
        float inv = 1.0f / (float)HWX;
        float mu  = ss[0] * inv;
        float var = sq[0] * inv - mu*mu;
        float sc  = gg[o] * rsqrtf(var + 1e-5f);
        g_bn[stage*2*CO + o]      = sc;
        g_bn[stage*2*CO + CO + o] = bb[o] - mu*sc;
    }
}

// ---------------- 6) depthwise 3x3 on act(C), float4 channels, 8 px/block ----------------
__global__ void k_dw(const float* __restrict__ Cin_, const float* __restrict__ dww,
                     float* __restrict__ Z, int stage) {
    __shared__ float dws[CO*9];
    int tid = threadIdx.x;          // 256
    int pg = tid >> 5;              // 0..7 pixel in block
    int cg = tid & 31;              // 0..31 channel group (4 ch)
    for (int i = tid; i < CO*9; i += 256) dws[i] = dww[i];
    __syncthreads();
    int p = blockIdx.x * 8 + pg;
    int h = p / WWD, w = p % WWD;
    int cb = cg * 4;
    float4 sc = *(const float4*)&g_bn[stage*2*CO + cb];
    float4 sh = *(const float4*)&g_bn[stage*2*CO + CO + cb];
    float4 acc = make_float4(0.f,0.f,0.f,0.f);
    #pragma unroll
    for (int t = 0; t < 9; t++) {
        int hh = h + t/3 - 1, ww = w + t%3 - 1;
        if (hh < 0 || hh >= HH || ww < 0 || ww >= WWD) continue;
        float4 v = *(const float4*)&Cin_[(hh*WWD + ww)*CO + cb];
        float ax = v.x*sc.x + sh.x; ax = (ax >= 0.f) ? ax : 0.01f*ax;
        float ay = v.y*sc.y + sh.y; ay = (ay >= 0.f) ? ay : 0.01f*ay;
        float az = v.z*sc.z + sh.z; az = (az >= 0.f) ? az : 0.01f*az;
        float aw = v.w*sc.w + sh.w; aw = (aw >= 0.f) ? aw : 0.01f*aw;
        acc.x += dws[(cb+0)*9+t] * ax;
        acc.y += dws[(cb+1)*9+t] * ay;
        acc.z += dws[(cb+2)*9+t] * az;
        acc.w += dws[(cb+3)*9+t] * aw;
    }
    *(float4*)&Z[p*CO + cb] = acc;
}

// ---------------- 7) final act + transpose to NCHW ----------------
__global__ void k_final(float* __restrict__ out) {
    __shared__ float s[32][33];
    int ptile = blockIdx.x * 32;
    int ctile = blockIdx.y * 32;
    int tx = threadIdx.x, ty = threadIdx.y;  // 32 x 8
    #pragma unroll
    for (int i = 0; i < 32; i += 8) {
        int p = ptile + ty + i, c = ctile + tx;
        float v = g_C3[p*CO + c];
        float a = v*g_bn[2*2*CO + c] + g_bn[2*2*CO + CO + c];
        a = (a >= 0.f) ? a : 0.01f*a;
        s[ty+i][tx] = a;
    }
    __syncthreads();
    #pragma unroll
    for (int i = 0; i < 32; i += 8)
        out[(ctile + ty + i)*HWX + ptile + tx] = s[tx][ty+i];
}

// ---------------- launch ----------------
extern "C" void kernel_launch(void* const* d_in, const int* in_sizes, int n_in,
                              void* d_out, int out_size) {
    const float* x        = (const float*)d_in[0];
    const float* x_range  = (const float*)d_in[1];
    const float* range_o  = (const float*)d_in[2];
    const float* w_reduce = (const float*)d_in[3];
    const float* g_r      = (const float*)d_in[4];
    const float* b_r      = (const float*)d_in[5];
    const float* dw1      = (const float*)d_in[6];
    const float* pw1      = (const float*)d_in[7];
    const float* g1       = (const float*)d_in[8];
    const float* b1       = (const float*)d_in[9];
    const float* dw2      = (const float*)d_in[10];
    const float* pw2      = (const float*)d_in[11];
    const float* g2       = (const float*)d_in[12];
    const float* b2       = (const float*)d_in[13];
    float* out = (float*)d_out;

    float *yT, *C1, *Z1, *C2, *Z2, *C3;
    cudaGetSymbolAddress((void**)&yT, g_yT);
    cudaGetSymbolAddress((void**)&C1, g_C1);
    cudaGetSymbolAddress((void**)&Z1, g_Z1);
    cudaGetSymbolAddress((void**)&C2, g_C2);
    cudaGetSymbolAddress((void**)&Z2, g_Z2);
    cudaGetSymbolAddress((void**)&C3, g_C3);

    k_pad_transpose<<<dim3((PP+31)/32, CIN/32), dim3(32,8)>>>(x);
    k_weights<<<(HWX+255)/256, 256>>>(x_range);
    k_gather<<<HWX/4, 256>>>(range_o);

    k_gemm<<<NBLK, 256>>>(yT, w_reduce, C1, CIN);
    k_bn_final<<<CO, 128>>>(g_r, b_r, 0);
    k_dw<<<HWX/8, 256>>>(C1, dw1, Z1, 0);

    k_gemm<<<NBLK, 256>>>(Z1, pw1, C2, CO);
    k_bn_final<<<CO, 128>>>(g1, b1, 1);
    k_dw<<<HWX/8, 256>>>(C2, dw2, Z2, 1);

    k_gemm<<<NBLK, 256>>>(Z2, pw2, C3, CO);
    k_bn_final<<<CO, 128>>>(g2, b2, 2);

    k_final<<<dim3(HWX/32, CO/32), dim3(32,8)>>>(out);
}

// round 12
// speedup vs baseline: 1.3299x; 1.2795x over previous
#include <cuda_runtime.h>
#include <cuda_bf16.h>
#include <math.h>
#include <stdint.h>

#define HH 64
#define WWD 192
#define HWX (HH*WWD)       // 12288
#define HP 66
#define WP 194
#define PP (HP*WP)         // 12804
#define CIN 256
#define CO 128
#define MTILE 128
#define NGB (HWX/MTILE)    // 96 gemm blocks
#define RS 40              // smem row pitch in bf16 (80B): conflict-free ldmatrix

// ---------------- scratch (device globals; no allocation) ----------------
__device__ float g_xT[PP*CIN];          // padded x, pixel-major (P, Cin)
__device__ int   g_gn[HWX];
__device__ int   g_gi[HWX*40];
__device__ float g_gw[HWX*40];
__device__ __nv_bfloat16 g_y1[HWX*CIN];   // gather out hi
__device__ __nv_bfloat16 g_y2[HWX*CIN];   // gather out lo
__device__ __nv_bfloat16 g_w1h[CO*CIN], g_w1l[CO*CIN];
__device__ __nv_bfloat16 g_w2h[CO*CO],  g_w2l[CO*CO];
__device__ __nv_bfloat16 g_w3h[CO*CO],  g_w3l[CO*CO];
__device__ __nv_bfloat16 g_z1h[HWX*CO], g_z1l[HWX*CO];
__device__ __nv_bfloat16 g_z2h[HWX*CO], g_z2l[HWX*CO];
__device__ float g_C1[HWX*CO];
__device__ float g_C2[HWX*CO];
__device__ float g_C3[HWX*CO];
__device__ float g_psum[NGB*CO];
__device__ float g_psq[NGB*CO];
__device__ float g_bn[3*2*CO];

// ---------------- helpers ----------------
__device__ __forceinline__ uint32_t s2u(const void* p) {
    uint32_t r;
    asm("{ .reg .u64 t; cvta.to.shared.u64 t, %1; cvt.u32.u64 %0, t; }" : "=r"(r) : "l"(p));
    return r;
}
__device__ __forceinline__ void ldmx4(uint32_t* r, uint32_t addr) {
    asm volatile("ldmatrix.sync.aligned.m8n8.x4.shared.b16 {%0,%1,%2,%3}, [%4];"
                 : "=r"(r[0]), "=r"(r[1]), "=r"(r[2]), "=r"(r[3]) : "r"(addr));
}
__device__ __forceinline__ void mma16816(float* d, const uint32_t* a, uint32_t b0, uint32_t b1) {
    asm volatile(
        "mma.sync.aligned.m16n8k16.row.col.f32.bf16.bf16.f32 "
        "{%0,%1,%2,%3}, {%4,%5,%6,%7}, {%8,%9}, {%0,%1,%2,%3};"
        : "+f"(d[0]), "+f"(d[1]), "+f"(d[2]), "+f"(d[3])
        : "r"(a[0]), "r"(a[1]), "r"(a[2]), "r"(a[3]), "r"(b0), "r"(b1));
}
__device__ __forceinline__ void split_bf16(float v, __nv_bfloat16& h, __nv_bfloat16& l) {
    h = __float2bfloat16(v);
    l = __float2bfloat16(v - __bfloat162float(h));
}

// ---------------- 1) pad + transpose x: (Cin,H,W) -> (P, Cin) ----------------
__global__ void k_pad_transpose(const float* __restrict__ x) {
    __shared__ float s[32][33];
    int ptile = blockIdx.x * 32;
    int ctile = blockIdx.y * 32;
    int tx = threadIdx.x, ty = threadIdx.y;   // 32 x 8
    #pragma unroll
    for (int i = 0; i < 32; i += 8) {
        int c = ctile + ty + i;
        int p = ptile + tx;
        float v = 0.f;
        if (p < PP) {
            int ph = p / WP, pw = p % WP;
            if (ph >= 1 && ph <= HH && pw >= 1 && pw <= WWD)
                v = x[c*HWX + (ph-1)*WWD + (pw-1)];
        }
        s[ty+i][tx] = v;
    }
    __syncthreads();
    #pragma unroll
    for (int i = 0; i < 32; i += 8) {
        int p = ptile + ty + i;
        if (p < PP) g_xT[p*CIN + ctile + tx] = s[tx][ty+i];
    }
}

// ---------------- 2) per-pixel compact (idx,weight,tap) list ----------------
__global__ void k_weights(const float* __restrict__ x_range) {
    int p = blockIdx.x * blockDim.x + threadIdx.x;
    if (p >= HWX) return;
    int h = p / WWD, w = p % WWD;
    float off = 3.0f / (1.0f + expf(-x_range[p]));
    float v0 = (float)((h+1)*WP + (w+1));
    const float PM1 = (float)(PP - 1);
    int   li[40];
    float lw[40];
    int cnt = 0;
    #pragma unroll
    for (int t = 0; t < 9; t++) {
        float xo = (float)(t % 3 - 1);
        float yo = (float)(t / 3 - 1);
        float pre   = v0 + xo + yo*(float)WP;
        float ofv   = off*xo + yo*(float)WP;
        float after = pre + ofv;
        float avf  = fminf(fmaxf(pre + floorf(ofv), 0.f), PM1);
        float avf1 = fminf(fmaxf(avf + xo, 0.f), PM1);
        float avc  = fminf(fmaxf(pre + ceilf(ofv), 0.f), PM1);
        float avc1 = fminf(fmaxf(avc + xo, 0.f), PM1);
        float s1 = fabsf((after - avf)  / (float)WP);
        float s2 = fabsf((avc1 - after) / (float)WP);
        int   id4[4];
        float w4[4];
        id4[0] = (int)avf;  w4[0] = s1 * fabsf(after - avf);
        id4[1] = (int)avf1; w4[1] = s1 * fabsf(avf1 - after);
        id4[2] = (int)avc1; w4[2] = s2 * fabsf(after - avc1);
        id4[3] = (int)avc;  w4[3] = s2 * fabsf(avc - after);
        int start = cnt;
        #pragma unroll
        for (int j = 0; j < 4; j++) {
            if (w4[j] == 0.f) continue;
            bool merged = false;
            for (int e = start; e < cnt; e++) {
                if (li[e] == (id4[j] | (t << 16))) { lw[e] += w4[j]; merged = true; break; }
            }
            if (!merged) { li[cnt] = id4[j] | (t << 16); lw[cnt] = w4[j]; cnt++; }
        }
    }
    g_gn[p] = cnt;
    for (int e = 0; e < cnt; e++) {
        g_gi[p*40 + e] = li[e];
        g_gw[p*40 + e] = lw[e];
    }
}

// ---------------- 3) gather + tap-reduce -> y hi/lo bf16 ----------------
__global__ void k_gather(const float* __restrict__ range_out) {
    __shared__ float rcs[CIN*9];
    __shared__ int   si[4][40];
    __shared__ float sw[4][40];
    __shared__ int   scnt[4];
    int tid = threadIdx.x;             // 256
    int sub = tid >> 6;
    int c4  = tid & 63;
    int p = blockIdx.x * 4 + sub;
    for (int i = tid; i < CIN*9; i += 256) rcs[i] = range_out[i];
    if (c4 == 0) scnt[sub] = g_gn[p];
    if (c4 < 40) { si[sub][c4] = g_gi[p*40 + c4]; sw[sub][c4] = g_gw[p*40 + c4]; }
    __syncthreads();
    int cnt = scnt[sub];
    int cb = c4 * 4;
    float4 rc[9];
    #pragma unroll
    for (int t = 0; t < 9; t++)
        rc[t] = make_float4(rcs[(cb+0)*9+t], rcs[(cb+1)*9+t], rcs[(cb+2)*9+t], rcs[(cb+3)*9+t]);
    float4 acc = make_float4(0.f,0.f,0.f,0.f);
    float4 sb  = make_float4(0.f,0.f,0.f,0.f);
    int curt = -1;
    for (int e = 0; e < cnt; e++) {
        int ent = si[sub][e];
        int idx = ent & 0xFFFF;
        int t   = ent >> 16;
        if (t != curt) {
            if (curt >= 0) {
                acc.x += rc[curt].x*sb.x; acc.y += rc[curt].y*sb.y;
                acc.z += rc[curt].z*sb.z; acc.w += rc[curt].w*sb.w;
            }
            sb = make_float4(0.f,0.f,0.f,0.f);
            curt = t;
        }
        float wv = sw[sub][e];
        float4 v = *(const float4*)&g_xT[idx*CIN + cb];
        sb.x += wv*v.x; sb.y += wv*v.y; sb.z += wv*v.z; sb.w += wv*v.w;
    }
    if (curt >= 0) {
        acc.x += rc[curt].x*sb.x; acc.y += rc[curt].y*sb.y;
        acc.z += rc[curt].z*sb.z; acc.w += rc[curt].w*sb.w;
    }
    __nv_bfloat162 h01, h23, l01, l23;
    split_bf16(acc.x, h01.x, l01.x); split_bf16(acc.y, h01.y, l01.y);
    split_bf16(acc.z, h23.x, l23.x); split_bf16(acc.w, h23.y, l23.y);
    *(__nv_bfloat162*)&g_y1[p*CIN + cb]     = h01;
    *(__nv_bfloat162*)&g_y1[p*CIN + cb + 2] = h23;
    *(__nv_bfloat162*)&g_y2[p*CIN + cb]     = l01;
    *(__nv_bfloat162*)&g_y2[p*CIN + cb + 2] = l23;
}

// ---------------- weight split ----------------
__global__ void k_wsplit(const float* __restrict__ w, __nv_bfloat16* __restrict__ h,
                         __nv_bfloat16* __restrict__ l, int n) {
    int i = blockIdx.x * 256 + threadIdx.x;
    if (i >= n) return;
    split_bf16(w[i], h[i], l[i]);
}

// ---------------- 4) mma.sync bf16 GEMM, 3-pass split: D = A1B1 + A2B1 + A1B2 ----------
// A[M,K], B[N=128,K] row-major bf16 (NT). Block 128x128, warps 4x2, warp tile 32x64,
// K-chunk 32, double-buffered smem with 80B row pitch.
__global__ __launch_bounds__(256) void k_gemm_tc(
    const __nv_bfloat16* __restrict__ Ah, const __nv_bfloat16* __restrict__ Al,
    const __nv_bfloat16* __restrict__ Bh, const __nv_bfloat16* __restrict__ Bl,
    float* __restrict__ C, int K)
{
    __shared__ __align__(16) __nv_bfloat16 sA[2][128*RS];
    __shared__ __align__(16) __nv_bfloat16 sB[2][128*RS];
    int t = threadIdx.x;            // 256
    int lane = t & 31, wid = t >> 5;
    int wm = wid >> 1, wn = wid & 1;
    int m0 = blockIdx.x * MTILE;

    int cpp = K >> 5;               // chunks per pass
    int nch = 3 * cpp;

    // global load mapping: v = t + i*256 over 512 16B-vectors; row = v>>2, c4 = v&3
    int lr = t >> 2, lc = (t & 3) * 8;      // i=0 part; i=1 adds 64 rows

    float acc[2][8][4];
    #pragma unroll
    for (int mi = 0; mi < 2; mi++)
        #pragma unroll
        for (int nj = 0; nj < 8; nj++)
            #pragma unroll
            for (int q = 0; q < 4; q++) acc[mi][nj][q] = 0.f;

    // ldmatrix lane address components (element offsets within tile)
    // A x4 for (mi,h): mat = lane>>3: row += (mat&1)*8, col += (mat>>1)*8
    int a_row = wm*32 + (lane & 7) + (((lane >> 3) & 1) << 3);
    int a_col = ((lane >> 4) & 1) << 3;
    // B x4 for (bj,h): mat: row(n) += (mat>>1)*8, col(k) += (mat&1)*8
    int b_row = wn*64 + (lane & 7) + (((lane >> 4) & 1) << 3);
    int b_col = ((lane >> 3) & 1) << 3;

    uint32_t sAu0 = s2u(&sA[0][0]), sBu0 = s2u(&sB[0][0]);
    const uint32_t bufstride = 128*RS*2;

    uint4 ra[2], rb[2];
    // prefetch chunk 0 (pass0: Ah,Bh, kc=0)
    {
        const uint4* As = (const uint4*)Ah;
        const uint4* Bs = (const uint4*)Bh;
        ra[0] = As[((m0 + lr)*K + lc) >> 3];
        ra[1] = As[((m0 + lr + 64)*K + lc) >> 3];
        rb[0] = Bs[(lr*K + lc) >> 3];
        rb[1] = Bs[((lr + 64)*K + lc) >> 3];
    }
    // store chunk 0 to buf 0
    *(uint4*)&sA[0][lr*RS + lc]        = ra[0];
    *(uint4*)&sA[0][(lr + 64)*RS + lc] = ra[1];
    *(uint4*)&sB[0][lr*RS + lc]        = rb[0];
    *(uint4*)&sB[0][(lr + 64)*RS + lc] = rb[1];
    __syncthreads();

    for (int c = 0; c < nch; c++) {
        // issue next chunk's global loads (latency hidden behind MMA)
        bool more = (c + 1 < nch);
        if (more) {
            int cn = c + 1;
            int pass = cn / cpp;
            int kc = (cn - pass*cpp) * 32;
            const uint4* As = (const uint4*)(pass == 2 ? Al : Ah);
            const uint4* Bs = (const uint4*)(pass == 1 ? Bl : Bh);
            ra[0] = As[((m0 + lr)*K + kc + lc) >> 3];
            ra[1] = As[((m0 + lr + 64)*K + kc + lc) >> 3];
            rb[0] = Bs[(lr*K + kc + lc) >> 3];
            rb[1] = Bs[((lr + 64)*K + kc + lc) >> 3];
        }
        // compute on buf c&1
        uint32_t aBase = sAu0 + (c & 1)*bufstride + (a_row*RS + a_col)*2;
        uint32_t bBase = sBu0 + (c & 1)*bufstride + (b_row*RS + b_col)*2;
        #pragma unroll
        for (int h = 0; h < 2; h++) {
            uint32_t afr[2][4];
            ldmx4(afr[0], aBase + (h*16)*2);
            ldmx4(afr[1], aBase + (16*RS + h*16)*2);
            uint32_t bfr[4][4];
            #pragma unroll
            for (int bj = 0; bj < 4; bj++)
                ldmx4(bfr[bj], bBase + (bj*16*RS + h*16)*2);
            #pragma unroll
            for (int mi = 0; mi < 2; mi++)
                #pragma unroll
                for (int nj = 0; nj < 8; nj++)
                    mma16816(acc[mi][nj], afr[mi],
                             bfr[nj >> 1][(nj & 1)*2], bfr[nj >> 1][(nj & 1)*2 + 1]);
        }
        if (more) {
            int nb = (c + 1) & 1;
            *(uint4*)&sA[nb][lr*RS + lc]        = ra[0];
            *(uint4*)&sA[nb][(lr + 64)*RS + lc] = ra[1];
            *(uint4*)&sB[nb][lr*RS + lc]        = rb[0];
            *(uint4*)&sB[nb][(lr + 64)*RS + lc] = rb[1];
        }
        __syncthreads();
    }

    // epilogue: write C (f32)
    int g = lane >> 2, tig = lane & 3;
    #pragma unroll
    for (int mi = 0; mi < 2; mi++) {
        int r0 = m0 + wm*32 + mi*16 + g;
        #pragma unroll
        for (int nj = 0; nj < 8; nj++) {
            int col = wn*64 + nj*8 + tig*2;
            *(float2*)&C[r0*CO + col]       = make_float2(acc[mi][nj][0], acc[mi][nj][1]);
            *(float2*)&C[(r0 + 8)*CO + col] = make_float2(acc[mi][nj][2], acc[mi][nj][3]);
        }
    }
}

// ---------------- 4b) per-block column sums of C (BN partials) ----------------
__global__ void k_colred(const float* __restrict__ C) {
    __shared__ float ss[2][CO], sq[2][CO];
    int t = threadIdx.x;           // 256
    int col = t & 127, seg = t >> 7;
    int m0 = blockIdx.x * MTILE + seg * 64;
    float s = 0.f, q = 0.f;
    for (int i = 0; i < 64; i++) {
        float v = C[(m0 + i)*CO + col];
        s += v; q += v*v;
    }
    ss[seg][col] = s; sq[seg][col] = q;
    __syncthreads();
    if (t < CO) {
        g_psum[blockIdx.x*CO + t] = ss[0][t] + ss[1][t];
        g_psq [blockIdx.x*CO + t] = sq[0][t] + sq[1][t];
    }
}

// ---------------- 5) BN finalize ----------------
__global__ void k_bn_final(const float* __restrict__ gg, const float* __restrict__ bb, int stage) {
    __shared__ float ss[128], sq[128];
    int o = blockIdx.x;
    int t = threadIdx.x;           // 128
    float s = 0.f, q = 0.f;
    for (int i = t; i < NGB; i += 128) { s += g_psum[i*CO + o]; q += g_psq[i*CO + o]; }
    ss[t] = s; sq[t] = q;
    __syncthreads();
    for (int st = 64; st > 0; st >>= 1) {
        if (t < st) { ss[t] += ss[t+st]; sq[t] += sq[t+st]; }
        __syncthreads();
    }
    if (t == 0) {
        float inv = 1.0f / (float)HWX;
        float mu  = ss[0] * inv;
        float var = sq[0] * inv - mu*mu;
        float sc  = gg[o] * rsqrtf(var + 1e-5f);
        g_bn[stage*2*CO + o]      = sc;
        g_bn[stage*2*CO + CO + o] = bb[o] - mu*sc;
    }
}

// ---------------- 6) depthwise 3x3 on act(C) -> bf16 hi/lo ----------------
__global__ void k_dw(const float* __restrict__ Cin_, const float* __restrict__ dww,
                     __nv_bfloat16* __restrict__ Zh, __nv_bfloat16* __restrict__ Zl,
                     int stage) {
    __shared__ float dws[CO*9];
    int tid = threadIdx.x;          // 256
    int pg = tid >> 5;
    int cg = tid & 31;
    for (int i = tid; i < CO*9; i += 256) dws[i] = dww[i];
    __syncthreads();
    int p = blockIdx.x * 8 + pg;
    int h = p / WWD, w = p % WWD;
    int cb = cg * 4;
    float4 sc = *(const float4*)&g_bn[stage*2*CO + cb];
    float4 sh = *(const float4*)&g_bn[stage*2*CO + CO + cb];
    float4 acc = make_float4(0.f,0.f,0.f,0.f);
    #pragma unroll
    for (int t = 0; t < 9; t++) {
        int hh = h + t/3 - 1, ww = w + t%3 - 1;
        if (hh < 0 || hh >= HH || ww < 0 || ww >= WWD) continue;
        float4 v = *(const float4*)&Cin_[(hh*WWD + ww)*CO + cb];
        float ax = v.x*sc.x + sh.x; ax = (ax >= 0.f) ? ax : 0.01f*ax;
        float ay = v.y*sc.y + sh.y; ay = (ay >= 0.f) ? ay : 0.01f*ay;
        float az = v.z*sc.z + sh.z; az = (az >= 0.f) ? az : 0.01f*az;
        float aw = v.w*sc.w + sh.w; aw = (aw >= 0.f) ? aw : 0.01f*aw;
        acc.x += dws[(cb+0)*9+t] * ax;
        acc.y += dws[(cb+1)*9+t] * ay;
        acc.z += dws[(cb+2)*9+t] * az;
        acc.w += dws[(cb+3)*9+t] * aw;
    }
    __nv_bfloat162 h01, h23, l01, l23;
    split_bf16(acc.x, h01.x, l01.x); split_bf16(acc.y, h01.y, l01.y);
    split_bf16(acc.z, h23.x, l23.x); split_bf16(acc.w, h23.y, l23.y);
    *(__nv_bfloat162*)&Zh[p*CO + cb]     = h01;
    *(__nv_bfloat162*)&Zh[p*CO + cb + 2] = h23;
    *(__nv_bfloat162*)&Zl[p*CO + cb]     = l01;
    *(__nv_bfloat162*)&Zl[p*CO + cb + 2] = l23;
}

// ---------------- 7) final act + transpose to NCHW ----------------
__global__ void k_final(float* __restrict__ out) {
    __shared__ float s[32][33];
    int ptile = blockIdx.x * 32;
    int ctile = blockIdx.y * 32;
    int tx = threadIdx.x, ty = threadIdx.y;  // 32 x 8
    #pragma unroll
    for (int i = 0; i < 32; i += 8) {
        int p = ptile + ty + i, c = ctile + tx;
        float v = g_C3[p*CO + c];
        float a = v*g_bn[2*2*CO + c] + g_bn[2*2*CO + CO + c];
        a = (a >= 0.f) ? a : 0.01f*a;
        s[ty+i][tx] = a;
    }
    __syncthreads();
    #pragma unroll
    for (int i = 0; i < 32; i += 8)
        out[(ctile + ty + i)*HWX + ptile + tx] = s[tx][ty+i];
}

// ---------------- launch ----------------
extern "C" void kernel_launch(void* const* d_in, const int* in_sizes, int n_in,
                              void* d_out, int out_size) {
    const float* x        = (const float*)d_in[0];
    const float* x_range  = (const float*)d_in[1];
    const float* range_o  = (const float*)d_in[2];
    const float* w_reduce = (const float*)d_in[3];
    const float* g_r      = (const float*)d_in[4];
    const float* b_r      = (const float*)d_in[5];
    const float* dw1      = (const float*)d_in[6];
    const float* pw1      = (const float*)d_in[7];
    const float* g1       = (const float*)d_in[8];
    const float* b1       = (const float*)d_in[9];
    const float* dw2      = (const float*)d_in[10];
    const float* pw2      = (const float*)d_in[11];
    const float* g2       = (const float*)d_in[12];
    const float* b2       = (const float*)d_in[13];
    float* out = (float*)d_out;

    float *C1, *C2, *C3;
    __nv_bfloat16 *y1, *y2, *w1h, *w1l, *w2h, *w2l, *w3h, *w3l, *z1h, *z1l, *z2h, *z2l;
    cudaGetSymbolAddress((void**)&C1, g_C1);
    cudaGetSymbolAddress((void**)&C2, g_C2);
    cudaGetSymbolAddress((void**)&C3, g_C3);
    cudaGetSymbolAddress((void**)&y1, g_y1);
    cudaGetSymbolAddress((void**)&y2, g_y2);
    cudaGetSymbolAddress((void**)&w1h, g_w1h);
    cudaGetSymbolAddress((void**)&w1l, g_w1l);
    cudaGetSymbolAddress((void**)&w2h, g_w2h);
    cudaGetSymbolAddress((void**)&w2l, g_w2l);
    cudaGetSymbolAddress((void**)&w3h, g_w3h);
    cudaGetSymbolAddress((void**)&w3l, g_w3l);
    cudaGetSymbolAddress((void**)&z1h, g_z1h);
    cudaGetSymbolAddress((void**)&z1l, g_z1l);
    cudaGetSymbolAddress((void**)&z2h, g_z2h);
    cudaGetSymbolAddress((void**)&z2l, g_z2l);

    k_pad_transpose<<<dim3((PP+31)/32, CIN/32), dim3(32,8)>>>(x);
    k_weights<<<(HWX+255)/256, 256>>>(x_range);
    k_wsplit<<<(CO*CIN+255)/256, 256>>>(w_reduce, w1h, w1l, CO*CIN);
    k_wsplit<<<(CO*CO+255)/256, 256>>>(pw1, w2h, w2l, CO*CO);
    k_wsplit<<<(CO*CO+255)/256, 256>>>(pw2, w3h, w3l, CO*CO);
    k_gather<<<HWX/4, 256>>>(range_o);

    k_gemm_tc<<<NGB, 256>>>(y1, y2, w1h, w1l, C1, CIN);
    k_colred<<<NGB, 256>>>(C1);
    k_bn_final<<<CO, 128>>>(g_r, b_r, 0);
    k_dw<<<HWX/8, 256>>>(C1, dw1, z1h, z1l, 0);

    k_gemm_tc<<<NGB, 256>>>(z1h, z1l, w2h, w2l, C2, CO);
    k_colred<<<NGB, 256>>>(C2);
    k_bn_final<<<CO, 128>>>(g1, b1, 1);
    k_dw<<<HWX/8, 256>>>(C2, dw2, z2h, z2l, 1);

    k_gemm_tc<<<NGB, 256>>>(z2h, z2l, w3h, w3l, C3, CO);
    k_colred<<<NGB, 256>>>(C3);
    k_bn_final<<<CO, 128>>>(g2, b2, 2);

    k_final<<<dim3(HWX/32, CO/32), dim3(32,8)>>>(out);
}

// round 13
// speedup vs baseline: 1.6662x; 1.2529x over previous
#include <cuda_runtime.h>
#include <cuda_bf16.h>
#include <math.h>
#include <stdint.h>

#define HH 64
#define WWD 192
#define HWX (HH*WWD)       // 12288
#define HP 66
#define WP 194
#define PP (HP*WP)         // 12804
#define CIN 256
#define CO 128
#define MT 64
#define NGB (HWX/MT)       // 192 gemm blocks
#define RS 40              // smem row pitch in bf16 (80B): conflict-free ldmatrix

// ---------------- scratch (device globals; no allocation) ----------------
__device__ float g_xT[PP*CIN];          // padded x, pixel-major (P, Cin)
__device__ int   g_gn[HWX];             // tap-entry count per pixel (6..9)
__device__ int4  g_tap[HWX*9];          // {base|tap<<16, w0, w1, w2(float bits)}
__device__ __nv_bfloat16 g_y1[HWX*CIN];   // gather out hi
__device__ __nv_bfloat16 g_y2[HWX*CIN];   // gather out lo
__device__ __nv_bfloat16 g_w1h[CO*CIN], g_w1l[CO*CIN];
__device__ __nv_bfloat16 g_w2h[CO*CO],  g_w2l[CO*CO];
__device__ __nv_bfloat16 g_w3h[CO*CO],  g_w3l[CO*CO];
__device__ __nv_bfloat16 g_z1h[HWX*CO], g_z1l[HWX*CO];
__device__ __nv_bfloat16 g_z2h[HWX*CO], g_z2l[HWX*CO];
__device__ float g_C1[HWX*CO];
__device__ float g_C2[HWX*CO];
__device__ float g_C3[HWX*CO];
__device__ float g_psum[NGB*CO];
__device__ float g_psq[NGB*CO];
__device__ float g_bn[3*2*CO];

// ---------------- helpers ----------------
__device__ __forceinline__ uint32_t s2u(const void* p) {
    uint32_t r;
    asm("{ .reg .u64 t; cvta.to.shared.u64 t, %1; cvt.u32.u64 %0, t; }" : "=r"(r) : "l"(p));
    return r;
}
__device__ __forceinline__ void ldmx4(uint32_t* r, uint32_t addr) {
    asm volatile("ldmatrix.sync.aligned.m8n8.x4.shared.b16 {%0,%1,%2,%3}, [%4];"
                 : "=r"(r[0]), "=r"(r[1]), "=r"(r[2]), "=r"(r[3]) : "r"(addr));
}
__device__ __forceinline__ void mma16816(float* d, const uint32_t* a, uint32_t b0, uint32_t b1) {
    asm volatile(
        "mma.sync.aligned.m16n8k16.row.col.f32.bf16.bf16.f32 "
        "{%0,%1,%2,%3}, {%4,%5,%6,%7}, {%8,%9}, {%0,%1,%2,%3};"
        : "+f"(d[0]), "+f"(d[1]), "+f"(d[2]), "+f"(d[3])
        : "r"(a[0]), "r"(a[1]), "r"(a[2]), "r"(a[3]), "r"(b0), "r"(b1));
}
__device__ __forceinline__ void split_bf16(float v, __nv_bfloat16& h, __nv_bfloat16& l) {
    h = __float2bfloat16(v);
    l = __float2bfloat16(v - __bfloat162float(h));
}

// ---------------- 1) pad + transpose x: (Cin,H,W) -> (P, Cin) ----------------
__global__ void k_pad_transpose(const float* __restrict__ x) {
    __shared__ float s[32][33];
    int ptile = blockIdx.x * 32;
    int ctile = blockIdx.y * 32;
    int tx = threadIdx.x, ty = threadIdx.y;   // 32 x 8
    #pragma unroll
    for (int i = 0; i < 32; i += 8) {
        int c = ctile + ty + i;
        int p = ptile + tx;
        float v = 0.f;
        if (p < PP) {
            int ph = p / WP, pw = p % WP;
            if (ph >= 1 && ph <= HH && pw >= 1 && pw <= WWD)
                v = x[c*HWX + (ph-1)*WWD + (pw-1)];
        }
        s[ty+i][tx] = v;
    }
    __syncthreads();
    #pragma unroll
    for (int i = 0; i < 32; i += 8) {
        int p = ptile + ty + i;
        if (p < PP) g_xT[p*CIN + ctile + tx] = s[tx][ty+i];
    }
}

// ---------------- 2) per-pixel dense tap windows ----------------
// Per tap: all 4 interp indices span <= 2 (clamp is monotone, ceil-floor<=1),
// so each tap compresses to (base, w[0..2]) with base clamped to <= P-3.
__global__ void k_weights(const float* __restrict__ x_range) {
    int p = blockIdx.x * blockDim.x + threadIdx.x;
    if (p >= HWX) return;
    int h = p / WWD, w = p % WWD;
    float off = 3.0f / (1.0f + expf(-x_range[p]));
    float v0 = (float)((h+1)*WP + (w+1));
    const float PM1 = (float)(PP - 1);
    int cnt = 0;
    #pragma unroll
    for (int t = 0; t < 9; t++) {
        float xo = (float)(t % 3 - 1);
        float yo = (float)(t / 3 - 1);
        float pre   = v0 + xo + yo*(float)WP;
        float ofv   = off*xo + yo*(float)WP;
        float after = pre + ofv;
        float avf  = fminf(fmaxf(pre + floorf(ofv), 0.f), PM1);
        float avf1 = fminf(fmaxf(avf + xo, 0.f), PM1);
        float avc  = fminf(fmaxf(pre + ceilf(ofv), 0.f), PM1);
        float avc1 = fminf(fmaxf(avc + xo, 0.f), PM1);
        float s1 = fabsf((after - avf)  / (float)WP);
        float s2 = fabsf((avc1 - after) / (float)WP);
        int   id4[4];
        float w4[4];
        id4[0] = (int)avf;  w4[0] = s1 * fabsf(after - avf);
        id4[1] = (int)avf1; w4[1] = s1 * fabsf(avf1 - after);
        id4[2] = (int)avc1; w4[2] = s2 * fabsf(after - avc1);
        id4[3] = (int)avc;  w4[3] = s2 * fabsf(avc - after);
        bool center = ((t % 3) == 1);
        bool any = (w4[0] != 0.f) | (w4[1] != 0.f) | (w4[2] != 0.f) | (w4[3] != 0.f);
        if (center && !any) continue;   // interior center taps: exactly zero
        int base = min(min(id4[0], id4[1]), min(id4[2], id4[3]));
        base = min(base, PP - 3);
        float w0 = 0.f, w1 = 0.f, w2 = 0.f;
        #pragma unroll
        for (int j = 0; j < 4; j++) {
            int d = id4[j] - base;
            w0 += (d == 0) ? w4[j] : 0.f;
            w1 += (d == 1) ? w4[j] : 0.f;
            w2 += (d == 2) ? w4[j] : 0.f;
        }
        g_tap[p*9 + cnt] = make_int4(base | (t << 16),
                                     __float_as_int(w0), __float_as_int(w1), __float_as_int(w2));
        cnt++;
    }
    g_gn[p] = cnt;
}

// ---------------- 3) gather: branch-free 6x3 window loads -> y hi/lo bf16 -----
__global__ void k_gather(const float* __restrict__ range_out) {
    __shared__ float rcs[9][CIN];      // tap-major: conflict-free float4 reads
    __shared__ int4  staps[4][9];
    __shared__ int   scnt[4];
    int tid = threadIdx.x;             // 256
    int sub = tid >> 6;
    int c4  = tid & 63;
    int pbase = blockIdx.x * 4;
    for (int i = tid; i < CIN*9; i += 256) rcs[i % 9][i / 9] = range_out[i];
    if (tid < 36) staps[tid / 9][tid % 9] = g_tap[(pbase + tid/9)*9 + tid%9];
    if (tid >= 64 && tid < 68) scnt[tid - 64] = g_gn[pbase + tid - 64];
    __syncthreads();
    int p = pbase + sub;
    int cb = c4 * 4;
    float4 acc = make_float4(0.f, 0.f, 0.f, 0.f);

#define GBODY(e) { \
        int4 en = staps[sub][e]; \
        int base = en.x & 0xFFFF; \
        int tap  = en.x >> 16; \
        float w0 = __int_as_float(en.y), w1 = __int_as_float(en.z), w2 = __int_as_float(en.w); \
        const float* rp = &g_xT[base*CIN + cb]; \
        float4 v0 = *(const float4*)rp; \
        float4 v1 = *(const float4*)(rp + CIN); \
        float4 v2 = *(const float4*)(rp + 2*CIN); \
        float4 rcv = *(const float4*)&rcs[tap][cb]; \
        acc.x += rcv.x * (w0*v0.x + w1*v1.x + w2*v2.x); \
        acc.y += rcv.y * (w0*v0.y + w1*v1.y + w2*v2.y); \
        acc.z += rcv.z * (w0*v0.z + w1*v1.z + w2*v2.z); \
        acc.w += rcv.w * (w0*v0.w + w1*v1.w + w2*v2.w); \
    }

    GBODY(0) GBODY(1) GBODY(2) GBODY(3) GBODY(4) GBODY(5)
    int cnt = scnt[sub];
    for (int e = 6; e < cnt; e++) GBODY(e)
#undef GBODY

    __nv_bfloat162 h01, h23, l01, l23;
    split_bf16(acc.x, h01.x, l01.x); split_bf16(acc.y, h01.y, l01.y);
    split_bf16(acc.z, h23.x, l23.x); split_bf16(acc.w, h23.y, l23.y);
    *(__nv_bfloat162*)&g_y1[p*CIN + cb]     = h01;
    *(__nv_bfloat162*)&g_y1[p*CIN + cb + 2] = h23;
    *(__nv_bfloat162*)&g_y2[p*CIN + cb]     = l01;
    *(__nv_bfloat162*)&g_y2[p*CIN + cb + 2] = l23;
}

// ---------------- weight splits, all three in one launch ----------------
__global__ void k_wsplit_all(const float* __restrict__ w1, const float* __restrict__ w2,
                             const float* __restrict__ w3) {
    int i = blockIdx.x * 256 + threadIdx.x;   // 0..65535
    if (i < CO*CIN) {
        split_bf16(w1[i], g_w1h[i], g_w1l[i]);
    } else if (i < CO*CIN + CO*CO) {
        int j = i - CO*CIN;
        split_bf16(w2[j], g_w2h[j], g_w2l[j]);
    } else {
        int j = i - CO*CIN - CO*CO;
        split_bf16(w3[j], g_w3h[j], g_w3l[j]);
    }
}

// ---------------- 4) mma.sync bf16 GEMM, 3-pass split: D = A1B1 + A2B1 + A1B2 ----
// Block 64x128, 8 warps (wm 0..1 x wn 0..3), warp tile 32x32, K-chunk 32,
// double-buffered smem, 80B row pitch. 2 blocks/SM -> grid 192 single wave.
__global__ __launch_bounds__(256, 2) void k_gemm_tc(
    const __nv_bfloat16* __restrict__ Ah, const __nv_bfloat16* __restrict__ Al,
    const __nv_bfloat16* __restrict__ Bh, const __nv_bfloat16* __restrict__ Bl,
    float* __restrict__ C, int K)
{
    __shared__ __align__(16) __nv_bfloat16 sA[2][MT*RS];
    __shared__ __align__(16) __nv_bfloat16 sB[2][128*RS];
    int t = threadIdx.x;            // 256
    int lane = t & 31, wid = t >> 5;
    int wm = wid >> 2, wn = wid & 3;
    int m0 = blockIdx.x * MT;

    int cpp = K >> 5;
    int nch = 3 * cpp;

    int lr = t >> 2, lc = (t & 3) * 8;   // A/B global-load row, k-offset

    float acc[2][4][4];
    #pragma unroll
    for (int mi = 0; mi < 2; mi++)
        #pragma unroll
        for (int nj = 0; nj < 4; nj++)
            #pragma unroll
            for (int q = 0; q < 4; q++) acc[mi][nj][q] = 0.f;

    int a_row = wm*32 + (lane & 7) + (((lane >> 3) & 1) << 3);
    int a_col = ((lane >> 4) & 1) << 3;
    int b_row = wn*32 + (lane & 7) + (((lane >> 4) & 1) << 3);
    int b_col = ((lane >> 3) & 1) << 3;

    uint32_t sAu0 = s2u(&sA[0][0]), sBu0 = s2u(&sB[0][0]);
    const uint32_t bufA = MT*RS*2, bufB = 128*RS*2;

    uint4 ra, rb0, rb1;
    {
        const uint4* As = (const uint4*)Ah;
        const uint4* Bs = (const uint4*)Bh;
        ra  = As[((m0 + lr)*K + lc) >> 3];
        rb0 = Bs[(lr*K + lc) >> 3];
        rb1 = Bs[((lr + 64)*K + lc) >> 3];
    }
    *(uint4*)&sA[0][lr*RS + lc]        = ra;
    *(uint4*)&sB[0][lr*RS + lc]        = rb0;
    *(uint4*)&sB[0][(lr + 64)*RS + lc] = rb1;
    __syncthreads();

    for (int c = 0; c < nch; c++) {
        bool more = (c + 1 < nch);
        if (more) {
            int cn = c + 1;
            int pass = cn / cpp;
            int kc = (cn - pass*cpp) * 32;
            const uint4* As = (const uint4*)(pass == 2 ? Al : Ah);
            const uint4* Bs = (const uint4*)(pass == 1 ? Bl : Bh);
            ra  = As[((m0 + lr)*K + kc + lc) >> 3];
            rb0 = Bs[(lr*K + kc + lc) >> 3];
            rb1 = Bs[((lr + 64)*K + kc + lc) >> 3];
        }
        uint32_t aBase = sAu0 + (c & 1)*bufA + (a_row*RS + a_col)*2;
        uint32_t bBase = sBu0 + (c & 1)*bufB + (b_row*RS + b_col)*2;
        #pragma unroll
        for (int h = 0; h < 2; h++) {
            uint32_t afr[2][4];
            ldmx4(afr[0], aBase + (h*16)*2);
            ldmx4(afr[1], aBase + (16*RS + h*16)*2);
            uint32_t bfr[2][4];
            ldmx4(bfr[0], bBase + (h*16)*2);
            ldmx4(bfr[1], bBase + (16*RS + h*16)*2);
            #pragma unroll
            for (int mi = 0; mi < 2; mi++)
                #pragma unroll
                for (int nj = 0; nj < 4; nj++)
                    mma16816(acc[mi][nj], afr[mi],
                             bfr[nj >> 1][(nj & 1)*2], bfr[nj >> 1][(nj & 1)*2 + 1]);
        }
        if (more) {
            int nb = (c + 1) & 1;
            *(uint4*)&sA[nb][lr*RS + lc]        = ra;
            *(uint4*)&sB[nb][lr*RS + lc]        = rb0;
            *(uint4*)&sB[nb][(lr + 64)*RS + lc] = rb1;
        }
        __syncthreads();
    }

    // epilogue: write C (f32)
    int g = lane >> 2, tig = lane & 3;
    #pragma unroll
    for (int mi = 0; mi < 2; mi++) {
        int r0 = m0 + wm*32 + mi*16 + g;
        #pragma unroll
        for (int nj = 0; nj < 4; nj++) {
            int col = wn*32 + nj*8 + tig*2;
            *(float2*)&C[r0*CO + col]       = make_float2(acc[mi][nj][0], acc[mi][nj][1]);
            *(float2*)&C[(r0 + 8)*CO + col] = make_float2(acc[mi][nj][2], acc[mi][nj][3]);
        }
    }
}

// ---------------- 4b) per-block column sums of C (BN partials) ----------------
__global__ void k_colred(const float* __restrict__ C) {
    __shared__ float ss[2][CO], sq[2][CO];
    int t = threadIdx.x;           // 256
    int col = t & 127, seg = t >> 7;
    int m0 = blockIdx.x * MT + seg * 32;
    float s = 0.f, q = 0.f;
    for (int i = 0; i < 32; i++) {
        float v = C[(m0 + i)*CO + col];
        s += v; q += v*v;
    }
    ss[seg][col] = s; sq[seg][col] = q;
    __syncthreads();
    if (t < CO) {
        g_psum[blockIdx.x*CO + t] = ss[0][t] + ss[1][t];
        g_psq [blockIdx.x*CO + t] = sq[0][t] + sq[1][t];
    }
}

// ---------------- 5) BN finalize ----------------
__global__ void k_bn_final(const float* __restrict__ gg, const float* __restrict__ bb, int stage) {
    __shared__ float ss[128], sq[128];
    int o = blockIdx.x;
    int t = threadIdx.x;           // 128
    float s = 0.f, q = 0.f;
    for (int i = t; i < NGB; i += 128) { s += g_psum[i*CO + o]; q += g_psq[i*CO + o]; }
    ss[t] = s; sq[t] = q;
    __syncthreads();
    for (int st = 64; st > 0; st >>= 1) {
        if (t < st) { ss[t] += ss[t+st]; sq[t] += sq[t+st]; }
        __syncthreads();
    }
    if (t == 0) {
        float inv = 1.0f / (float)HWX;
        float mu  = ss[0] * inv;
        float var = sq[0] * inv - mu*mu;
        float sc  = gg[o] * rsqrtf(var + 1e-5f);
        g_bn[stage*2*CO + o]      = sc;
        g_bn[stage*2*CO + CO + o] = bb[o] - mu*sc;
    }
}

// ---------------- 6) depthwise 3x3 on act(C) -> bf16 hi/lo ----------------
__global__ void k_dw(const float* __restrict__ Cin_, const float* __restrict__ dww,
                     __nv_bfloat16* __restrict__ Zh, __nv_bfloat16* __restrict__ Zl,
                     int stage) {
    __shared__ float dws[CO*9];
    int tid = threadIdx.x;          // 256
    int pg = tid >> 5;
    int cg = tid & 31;
    for (int i = tid; i < CO*9; i += 256) dws[i] = dww[i];
    __syncthreads();
    int p = blockIdx.x * 8 + pg;
    int h = p / WWD, w = p % WWD;
    int cb = cg * 4;
    float4 sc = *(const float4*)&g_bn[stage*2*CO + cb];
    float4 sh = *(const float4*)&g_bn[stage*2*CO + CO + cb];
    float4 acc = make_float4(0.f,0.f,0.f,0.f);
    #pragma unroll
    for (int t = 0; t < 9; t++) {
        int hh = h + t/3 - 1, ww = w + t%3 - 1;
        if (hh < 0 || hh >= HH || ww < 0 || ww >= WWD) continue;
        float4 v = *(const float4*)&Cin_[(hh*WWD + ww)*CO + cb];
        float ax = v.x*sc.x + sh.x; ax = (ax >= 0.f) ? ax : 0.01f*ax;
        float ay = v.y*sc.y + sh.y; ay = (ay >= 0.f) ? ay : 0.01f*ay;
        float az = v.z*sc.z + sh.z; az = (az >= 0.f) ? az : 0.01f*az;
        float aw = v.w*sc.w + sh.w; aw = (aw >= 0.f) ? aw : 0.01f*aw;
        acc.x += dws[(cb+0)*9+t] * ax;
        acc.y += dws[(cb+1)*9+t] * ay;
        acc.z += dws[(cb+2)*9+t] * az;
        acc.w += dws[(cb+3)*9+t] * aw;
    }
    __nv_bfloat162 h01, h23, l01, l23;
    split_bf16(acc.x, h01.x, l01.x); split_bf16(acc.y, h01.y, l01.y);
    split_bf16(acc.z, h23.x, l23.x); split_bf16(acc.w, h23.y, l23.y);
    *(__nv_bfloat162*)&Zh[p*CO + cb]     = h01;
    *(__nv_bfloat162*)&Zh[p*CO + cb + 2] = h23;
    *(__nv_bfloat162*)&Zl[p*CO + cb]     = l01;
    *(__nv_bfloat162*)&Zl[p*CO + cb + 2] = l23;
}

// ---------------- 7) final act + transpose to NCHW ----------------
__global__ void k_final(float* __restrict__ out) {
    __shared__ float s[32][33];
    int ptile = blockIdx.x * 32;
    int ctile = blockIdx.y * 32;
    int tx = threadIdx.x, ty = threadIdx.y;  // 32 x 8
    #pragma unroll
    for (int i = 0; i < 32; i += 8) {
        int p = ptile + ty + i, c = ctile + tx;
        float v = g_C3[p*CO + c];
        float a = v*g_bn[2*2*CO + c] + g_bn[2*2*CO + CO + c];
        a = (a >= 0.f) ? a : 0.01f*a;
        s[ty+i][tx] = a;
    }
    __syncthreads();
    #pragma unroll
    for (int i = 0; i < 32; i += 8)
        out[(ctile + ty + i)*HWX + ptile + tx] = s[tx][ty+i];
}

// ---------------- launch ----------------
extern "C" void kernel_launch(void* const* d_in, const int* in_sizes, int n_in,
                              void* d_out, int out_size) {
    const float* x        = (const float*)d_in[0];
    const float* x_range  = (const float*)d_in[1];
    const float* range_o  = (const float*)d_in[2];
    const float* w_reduce = (const float*)d_in[3];
    const float* g_r      = (const float*)d_in[4];
    const float* b_r      = (const float*)d_in[5];
    const float* dw1      = (const float*)d_in[6];
    const float* pw1      = (const float*)d_in[7];
    const float* g1       = (const float*)d_in[8];
    const float* b1       = (const float*)d_in[9];
    const float* dw2      = (const float*)d_in[10];
    const float* pw2      = (const float*)d_in[11];
    const float* g2       = (const float*)d_in[12];
    const float* b2       = (const float*)d_in[13];
    float* out = (float*)d_out;

    float *C1, *C2, *C3;
    __nv_bfloat16 *y1, *y2, *w1h, *w1l, *w2h, *w2l, *w3h, *w3l, *z1h, *z1l, *z2h, *z2l;
    cudaGetSymbolAddress((void**)&C1, g_C1);
    cudaGetSymbolAddress((void**)&C2, g_C2);
    cudaGetSymbolAddress((void**)&C3, g_C3);
    cudaGetSymbolAddress((void**)&y1, g_y1);
    cudaGetSymbolAddress((void**)&y2, g_y2);
    cudaGetSymbolAddress((void**)&w1h, g_w1h);
    cudaGetSymbolAddress((void**)&w1l, g_w1l);
    cudaGetSymbolAddress((void**)&w2h, g_w2h);
    cudaGetSymbolAddress((void**)&w2l, g_w2l);
    cudaGetSymbolAddress((void**)&w3h, g_w3h);
    cudaGetSymbolAddress((void**)&w3l, g_w3l);
    cudaGetSymbolAddress((void**)&z1h, g_z1h);
    cudaGetSymbolAddress((void**)&z1l, g_z1l);
    cudaGetSymbolAddress((void**)&z2h, g_z2h);
    cudaGetSymbolAddress((void**)&z2l, g_z2l);

    k_pad_transpose<<<dim3((PP+31)/32, CIN/32), dim3(32,8)>>>(x);
    k_weights<<<(HWX+255)/256, 256>>>(x_range);
    k_wsplit_all<<<256, 256>>>(w_reduce, pw1, pw2);
    k_gather<<<HWX/4, 256>>>(range_o);

    k_gemm_tc<<<NGB, 256>>>(y1, y2, w1h, w1l, C1, CIN);
    k_colred<<<NGB, 256>>>(C1);
    k_bn_final<<<CO, 128>>>(g_r, b_r, 0);
    k_dw<<<HWX/8, 256>>>(C1, dw1, z1h, z1l, 0);

    k_gemm_tc<<<NGB, 256>>>(z1h, z1l, w2h, w2l, C2, CO);
    k_colred<<<NGB, 256>>>(C2);
    k_bn_final<<<CO, 128>>>(g1, b1, 1);
    k_dw<<<HWX/8, 256>>>(C2, dw2, z2h, z2l, 1);

    k_gemm_tc<<<NGB, 256>>>(z2h, z2l, w3h, w3l, C3, CO);
    k_colred<<<NGB, 256>>>(C3);
    k_bn_final<<<CO, 128>>>(g2, b2, 2);

    k_final<<<dim3(HWX/32, CO/32), dim3(32,8)>>>(out);
}

// round 16
// speedup vs baseline: 1.8236x; 1.0945x over previous
#include <cuda_runtime.h>
#include <cuda_bf16.h>
#include <math.h>
#include <stdint.h>

#define HH 64
#define WWD 192
#define HWX (HH*WWD)       // 12288
#define HP 66
#define WP 194
#define PP (HP*WP)         // 12804
#define CIN 256
#define CO 128
#define MT 64
#define NGB (HWX/MT)       // 192 gemm blocks
#define RS 40              // smem row pitch in bf16 (80B): conflict-free ldmatrix

// ---------------- scratch (device globals; no allocation) ----------------
__device__ float g_xT[PP*CIN];          // padded x, pixel-major (P, Cin)
__device__ int   g_gn[HWX];             // tap-entry count per pixel (6..9)
__device__ int4  g_tap[HWX*9];          // slots 0-5: side taps (fixed); 6+: border centers
__device__ float g_rcT[9*CIN];          // range_out transposed tap-major
__device__ __nv_bfloat16 g_y1[HWX*CIN];   // gather out hi
__device__ __nv_bfloat16 g_y2[HWX*CIN];   // gather out lo
__device__ __nv_bfloat16 g_w1h[CO*CIN], g_w1l[CO*CIN];
__device__ __nv_bfloat16 g_w2h[CO*CO],  g_w2l[CO*CO];
__device__ __nv_bfloat16 g_w3h[CO*CO],  g_w3l[CO*CO];
__device__ __nv_bfloat16 g_z1h[HWX*CO], g_z1l[HWX*CO];
__device__ __nv_bfloat16 g_z2h[HWX*CO], g_z2l[HWX*CO];
__device__ float g_C1[HWX*CO];
__device__ float g_C2[HWX*CO];
__device__ float g_C3[HWX*CO];
__device__ float g_psum[NGB*CO];
__device__ float g_psq[NGB*CO];
__device__ float g_bn[3*2*CO];

// ---------------- helpers ----------------
__device__ __forceinline__ uint32_t s2u(const void* p) {
    uint32_t r;
    asm("{ .reg .u64 t; cvta.to.shared.u64 t, %1; cvt.u32.u64 %0, t; }" : "=r"(r) : "l"(p));
    return r;
}
__device__ __forceinline__ void ldmx4(uint32_t* r, uint32_t addr) {
    asm volatile("ldmatrix.sync.aligned.m8n8.x4.shared.b16 {%0,%1,%2,%3}, [%4];"
                 : "=r"(r[0]), "=r"(r[1]), "=r"(r[2]), "=r"(r[3]) : "r"(addr));
}
__device__ __forceinline__ void mma16816(float* d, const uint32_t* a, uint32_t b0, uint32_t b1) {
    asm volatile(
        "mma.sync.aligned.m16n8k16.row.col.f32.bf16.bf16.f32 "
        "{%0,%1,%2,%3}, {%4,%5,%6,%7}, {%8,%9}, {%0,%1,%2,%3};"
        : "+f"(d[0]), "+f"(d[1]), "+f"(d[2]), "+f"(d[3])
        : "r"(a[0]), "r"(a[1]), "r"(a[2]), "r"(a[3]), "r"(b0), "r"(b1));
}
__device__ __forceinline__ void split_bf16(float v, __nv_bfloat16& h, __nv_bfloat16& l) {
    h = __float2bfloat16(v);
    l = __float2bfloat16(v - __bfloat162float(h));
}

// ---------------- 1) pad + transpose x: (Cin,H,W) -> (P, Cin) ----------------
__global__ void k_pad_transpose(const float* __restrict__ x) {
    __shared__ float s[32][33];
    int ptile = blockIdx.x * 32;
    int ctile = blockIdx.y * 32;
    int tx = threadIdx.x, ty = threadIdx.y;   // 32 x 8
    #pragma unroll
    for (int i = 0; i < 32; i += 8) {
        int c = ctile + ty + i;
        int p = ptile + tx;
        float v = 0.f;
        if (p < PP) {
            int ph = p / WP, pw = p % WP;
            if (ph >= 1 && ph <= HH && pw >= 1 && pw <= WWD)
                v = x[c*HWX + (ph-1)*WWD + (pw-1)];
        }
        s[ty+i][tx] = v;
    }
    __syncthreads();
    #pragma unroll
    for (int i = 0; i < 32; i += 8) {
        int p = ptile + ty + i;
        if (p < PP) g_xT[p*CIN + ctile + tx] = s[tx][ty+i];
    }
}

// ---------------- 2) per-pixel dense tap windows ----------------
// Side taps (t%3 != 1) -> fixed slots 0..5 (always nonzero).
// Center taps (border rows only) -> appended at slots 6+ with tap id in bits 16+.
__global__ void k_weights(const float* __restrict__ x_range) {
    int p = blockIdx.x * blockDim.x + threadIdx.x;
    if (p >= HWX) return;
    int h = p / WWD, w = p % WWD;
    float off = 3.0f / (1.0f + expf(-x_range[p]));
    float v0 = (float)((h+1)*WP + (w+1));
    const float PM1 = (float)(PP - 1);
    int cc = 6;
    #pragma unroll
    for (int t = 0; t < 9; t++) {
        float xo = (float)(t % 3 - 1);
        float yo = (float)(t / 3 - 1);
        float pre   = v0 + xo + yo*(float)WP;
        float ofv   = off*xo + yo*(float)WP;
        float after = pre + ofv;
        float avf  = fminf(fmaxf(pre + floorf(ofv), 0.f), PM1);
        float avf1 = fminf(fmaxf(avf + xo, 0.f), PM1);
        float avc  = fminf(fmaxf(pre + ceilf(ofv), 0.f), PM1);
        float avc1 = fminf(fmaxf(avc + xo, 0.f), PM1);
        float s1 = fabsf((after - avf)  / (float)WP);
        float s2 = fabsf((avc1 - after) / (float)WP);
        int   id4[4];
        float w4[4];
        id4[0] = (int)avf;  w4[0] = s1 * fabsf(after - avf);
        id4[1] = (int)avf1; w4[1] = s1 * fabsf(avf1 - after);
        id4[2] = (int)avc1; w4[2] = s2 * fabsf(after - avc1);
        id4[3] = (int)avc;  w4[3] = s2 * fabsf(avc - after);
        bool center = ((t % 3) == 1);
        bool any = (w4[0] != 0.f) | (w4[1] != 0.f) | (w4[2] != 0.f) | (w4[3] != 0.f);
        if (center && !any) continue;   // interior center taps: exactly zero
        int base = min(min(id4[0], id4[1]), min(id4[2], id4[3]));
        base = min(base, PP - 3);
        float w0 = 0.f, w1 = 0.f, w2 = 0.f;
        #pragma unroll
        for (int j = 0; j < 4; j++) {
            int d = id4[j] - base;
            w0 += (d == 0) ? w4[j] : 0.f;
            w1 += (d == 1) ? w4[j] : 0.f;
            w2 += (d == 2) ? w4[j] : 0.f;
        }
        int slot;
        if (!center) {
            // t in {0,2,3,5,6,8} -> slot {0,1,2,3,4,5}
            slot = (t > 1 ? t - 1 : t);          // 0,1,2,4,5,7
            slot = (slot > 2 ? slot - 1 : slot); // 0,1,2,3,4,6
            slot = (slot > 4 ? slot - 1 : slot); // 0,1,2,3,4,5
        } else {
            slot = cc++;
        }
        g_tap[p*9 + slot] = make_int4(base | (t << 16),
                                      __float_as_int(w0), __float_as_int(w1), __float_as_int(w2));
    }
    g_gn[p] = cc;
}

// ---------------- 3) gather: warp-autonomous, zero smem ----------------
// Warp gw -> pixel pair (gw>>1), channel half (gw&1). 4 ch/lane.
__global__ __launch_bounds__(256) void k_gather() {
    int tid = threadIdx.x, lane = tid & 31, wid = tid >> 5;
    int gw = blockIdx.x * 8 + wid;            // 0..12287
    int half = gw & 1;
    int pg = gw >> 1;                         // 0..6143
    int cb = half * 128 + lane * 4;
    // side-tap range coefficients, statically indexed (taps 0,2,3,5,6,8)
    float4 rcv[6];
    rcv[0] = *(const float4*)&g_rcT[0*CIN + cb];
    rcv[1] = *(const float4*)&g_rcT[2*CIN + cb];
    rcv[2] = *(const float4*)&g_rcT[3*CIN + cb];
    rcv[3] = *(const float4*)&g_rcT[5*CIN + cb];
    rcv[4] = *(const float4*)&g_rcT[6*CIN + cb];
    rcv[5] = *(const float4*)&g_rcT[8*CIN + cb];
    #pragma unroll
    for (int pi = 0; pi < 2; pi++) {
        int p = pg * 2 + pi;
        int cnt = g_gn[p];                    // warp-uniform
        float4 acc = make_float4(0.f, 0.f, 0.f, 0.f);
        #pragma unroll
        for (int s = 0; s < 6; s++) {
            int4 en = g_tap[p*9 + s];         // warp-uniform
            int base = en.x & 0xFFFF;
            float w0 = __int_as_float(en.y), w1 = __int_as_float(en.z), w2 = __int_as_float(en.w);
            const float* rp = &g_xT[base*CIN + cb];
            float4 v0 = *(const float4*)rp;
            float4 v1 = *(const float4*)(rp + CIN);
            float4 v2 = *(const float4*)(rp + 2*CIN);
            float4 r = rcv[s];
            acc.x += r.x * (w0*v0.x + w1*v1.x + w2*v2.x);
            acc.y += r.y * (w0*v0.y + w1*v1.y + w2*v2.y);
            acc.z += r.z * (w0*v0.z + w1*v1.z + w2*v2.z);
            acc.w += r.w * (w0*v0.w + w1*v1.w + w2*v2.w);
        }
        for (int e = 6; e < cnt; e++) {       // border-row center taps only
            int4 en = g_tap[p*9 + e];
            int base = en.x & 0xFFFF;
            int tap  = en.x >> 16;
            float w0 = __int_as_float(en.y), w1 = __int_as_float(en.z), w2 = __int_as_float(en.w);
            const float* rp = &g_xT[base*CIN + cb];
            float4 v0 = *(const float4*)rp;
            float4 v1 = *(const float4*)(rp + CIN);
            float4 v2 = *(const float4*)(rp + 2*CIN);
            float4 r = *(const float4*)&g_rcT[tap*CIN + cb];
            acc.x += r.x * (w0*v0.x + w1*v1.x + w2*v2.x);
            acc.y += r.y * (w0*v0.y + w1*v1.y + w2*v2.y);
            acc.z += r.z * (w0*v0.z + w1*v1.z + w2*v2.z);
            acc.w += r.w * (w0*v0.w + w1*v1.w + w2*v2.w);
        }
        union { __nv_bfloat162 b2[2]; uint2 u; } hv, lv;
        split_bf16(acc.x, hv.b2[0].x, lv.b2[0].x);
        split_bf16(acc.y, hv.b2[0].y, lv.b2[0].y);
        split_bf16(acc.z, hv.b2[1].x, lv.b2[1].x);
        split_bf16(acc.w, hv.b2[1].y, lv.b2[1].y);
        *(uint2*)&g_y1[p*CIN + cb] = hv.u;
        *(uint2*)&g_y2[p*CIN + cb] = lv.u;
    }
}

// ---------------- weight splits + rc transpose, one launch ----------------
__global__ void k_wsplit_all(const float* __restrict__ w1, const float* __restrict__ w2,
                             const float* __restrict__ w3, const float* __restrict__ rc) {
    int i = blockIdx.x * 256 + threadIdx.x;   // 0..67839
    if (i < CO*CIN) {
        split_bf16(w1[i], g_w1h[i], g_w1l[i]);
    } else if (i < CO*CIN + CO*CO) {
        int j = i - CO*CIN;
        split_bf16(w2[j], g_w2h[j], g_w2l[j]);
    } else if (i < CO*CIN + 2*CO*CO) {
        int j = i - CO*CIN - CO*CO;
        split_bf16(w3[j], g_w3h[j], g_w3l[j]);
    } else {
        int j = i - (CO*CIN + 2*CO*CO);       // 0..2303
        int t = j >> 8, c = j & 255;
        g_rcT[t*CIN + c] = rc[c*9 + t];
    }
}

// ---------------- 4) mma.sync bf16 GEMM + fused BN column partials ----------
// Block 64x128, 8 warps (wm 0..1 x wn 0..3), warp tile 32x32, K-chunk 32,
// double-buffered smem, 80B row pitch. Epilogue reduces its own 64 rows.
__global__ __launch_bounds__(256, 2) void k_gemm_tc(
    const __nv_bfloat16* __restrict__ Ah, const __nv_bfloat16* __restrict__ Al,
    const __nv_bfloat16* __restrict__ Bh, const __nv_bfloat16* __restrict__ Bl,
    float* __restrict__ C, int K)
{
    __shared__ __align__(16) union SmU {
        struct { __nv_bfloat16 A[2][MT*RS]; __nv_bfloat16 B[2][128*RS]; } m;
        struct { float sred[16][CO]; float sqred[16][CO]; } r;
    } sm;
    int t = threadIdx.x;            // 256
    int lane = t & 31, wid = t >> 5;
    int wm = wid >> 2, wn = wid & 3;
    int m0 = blockIdx.x * MT;

    int cpp = K >> 5;
    int nch = 3 * cpp;

    int lr = t >> 2, lc = (t & 3) * 8;   // A/B global-load row, k-offset

    float acc[2][4][4];
    #pragma unroll
    for (int mi = 0; mi < 2; mi++)
        #pragma unroll
        for (int nj = 0; nj < 4; nj++)
            #pragma unroll
            for (int q = 0; q < 4; q++) acc[mi][nj][q] = 0.f;

    int a_row = wm*32 + (lane & 7) + (((lane >> 3) & 1) << 3);
    int a_col = ((lane >> 4) & 1) << 3;
    int b_row = wn*32 + (lane & 7) + (((lane >> 4) & 1) << 3);
    int b_col = ((lane >> 3) & 1) << 3;

    uint32_t sAu0 = s2u(&sm.m.A[0][0]), sBu0 = s2u(&sm.m.B[0][0]);
    const uint32_t bufA = MT*RS*2, bufB = 128*RS*2;

    uint4 ra, rb0, rb1;
    {
        const uint4* As = (const uint4*)Ah;
        const uint4* Bs = (const uint4*)Bh;
        ra  = As[((m0 + lr)*K + lc) >> 3];
        rb0 = Bs[(lr*K + lc) >> 3];
        rb1 = Bs[((lr + 64)*K + lc) >> 3];
    }
    *(uint4*)&sm.m.A[0][lr*RS + lc]        = ra;
    *(uint4*)&sm.m.B[0][lr*RS + lc]        = rb0;
    *(uint4*)&sm.m.B[0][(lr + 64)*RS + lc] = rb1;
    __syncthreads();

    for (int c = 0; c < nch; c++) {
        bool more = (c + 1 < nch);
        if (more) {
            int cn = c + 1;
            int pass = cn / cpp;
            int kc = (cn - pass*cpp) * 32;
            const uint4* As = (const uint4*)(pass == 2 ? Al : Ah);
            const uint4* Bs = (const uint4*)(pass == 1 ? Bl : Bh);
            ra  = As[((m0 + lr)*K + kc + lc) >> 3];
            rb0 = Bs[(lr*K + kc + lc) >> 3];
            rb1 = Bs[((lr + 64)*K + kc + lc) >> 3];
        }
        uint32_t aBase = sAu0 + (c & 1)*bufA + (a_row*RS + a_col)*2;
        uint32_t bBase = sBu0 + (c & 1)*bufB + (b_row*RS + b_col)*2;
        #pragma unroll
        for (int h = 0; h < 2; h++) {
            uint32_t afr[2][4];
            ldmx4(afr[0], aBase + (h*16)*2);
            ldmx4(afr[1], aBase + (16*RS + h*16)*2);
            uint32_t bfr[2][4];
            ldmx4(bfr[0], bBase + (h*16)*2);
            ldmx4(bfr[1], bBase + (16*RS + h*16)*2);
            #pragma unroll
            for (int mi = 0; mi < 2; mi++)
                #pragma unroll
                for (int nj = 0; nj < 4; nj++)
                    mma16816(acc[mi][nj], afr[mi],
                             bfr[nj >> 1][(nj & 1)*2], bfr[nj >> 1][(nj & 1)*2 + 1]);
        }
        if (more) {
            int nb = (c + 1) & 1;
            *(uint4*)&sm.m.A[nb][lr*RS + lc]        = ra;
            *(uint4*)&sm.m.B[nb][lr*RS + lc]        = rb0;
            *(uint4*)&sm.m.B[nb][(lr + 64)*RS + lc] = rb1;
        }
        __syncthreads();
    }

    // epilogue: write C + per-thread column partials over this thread's 4 rows
    int g = lane >> 2, tig = lane & 3;
    float cs[4][2], cq[4][2];
    #pragma unroll
    for (int nj = 0; nj < 4; nj++)
        #pragma unroll
        for (int b = 0; b < 2; b++) { cs[nj][b] = 0.f; cq[nj][b] = 0.f; }
    #pragma unroll
    for (int mi = 0; mi < 2; mi++) {
        int r0 = m0 + wm*32 + mi*16 + g;
        #pragma unroll
        for (int nj = 0; nj < 4; nj++) {
            int col = wn*32 + nj*8 + tig*2;
            *(float2*)&C[r0*CO + col]       = make_float2(acc[mi][nj][0], acc[mi][nj][1]);
            *(float2*)&C[(r0 + 8)*CO + col] = make_float2(acc[mi][nj][2], acc[mi][nj][3]);
            #pragma unroll
            for (int b = 0; b < 2; b++) {
                float v0 = acc[mi][nj][b], v1 = acc[mi][nj][2 + b];
                cs[nj][b] += v0 + v1;
                cq[nj][b] += v0*v0 + v1*v1;
            }
        }
    }
    // deterministic block reduce (overlay union; mainloop smem no longer read)
    int r16 = wm*8 + g;
    #pragma unroll
    for (int nj = 0; nj < 4; nj++)
        #pragma unroll
        for (int b = 0; b < 2; b++) {
            int col = wn*32 + nj*8 + tig*2 + b;
            sm.r.sred[r16][col]  = cs[nj][b];
            sm.r.sqred[r16][col] = cq[nj][b];
        }
    __syncthreads();
    if (t < CO) {
        float ts = 0.f, tq = 0.f;
        #pragma unroll
        for (int r = 0; r < 16; r++) { ts += sm.r.sred[r][t]; tq += sm.r.sqred[r][t]; }
        g_psum[blockIdx.x*CO + t] = ts;
        g_psq [blockIdx.x*CO + t] = tq;
    }
}

// ---------------- 5) BN finalize ----------------
__global__ void k_bn_final(const float* __restrict__ gg, const float* __restrict__ bb, int stage) {
    __shared__ float ss[128], sq[128];
    int o = blockIdx.x;
    int t = threadIdx.x;           // 128
    float s = 0.f, q = 0.f;
    for (int i = t; i < NGB; i += 128) { s += g_psum[i*CO + o]; q += g_psq[i*CO + o]; }
    ss[t] = s; sq[t] = q;
    __syncthreads();
    for (int st = 64; st > 0; st >>= 1) {
        if (t < st) { ss[t] += ss[t+st]; sq[t] += sq[t+st]; }
        __syncthreads();
    }
    if (t == 0) {
        float inv = 1.0f / (float)HWX;
        float mu  = ss[0] * inv;
        float var = sq[0] * inv - mu*mu;
        float sc  = gg[o] * rsqrtf(var + 1e-5f);
        g_bn[stage*2*CO + o]      = sc;
        g_bn[stage*2*CO + CO + o] = bb[o] - mu*sc;
    }
}

// ---------------- 6) depthwise 3x3 on act(C) -> bf16 hi/lo ----------------
__global__ void k_dw(const float* __restrict__ Cin_, const float* __restrict__ dww,
                     __nv_bfloat16* __restrict__ Zh, __nv_bfloat16* __restrict__ Zl,
                     int stage) {
    __shared__ float dws[CO*9];
    int tid = threadIdx.x;          // 256
    int pg = tid >> 5;
    int cg = tid & 31;
    for (int i = tid; i < CO*9; i += 256) dws[i] = dww[i];
    __syncthreads();
    int p = blockIdx.x * 8 + pg;
    int h = p / WWD, w = p % WWD;
    int cb = cg * 4;
    float4 sc = *(const float4*)&g_bn[stage*2*CO + cb];
    float4 sh = *(const float4*)&g_bn[stage*2*CO + CO + cb];
    float4 acc = make_float4(0.f,0.f,0.f,0.f);
    #pragma unroll
    for (int t = 0; t < 9; t++) {
        int hh = h + t/3 - 1, ww = w + t%3 - 1;
        if (hh < 0 || hh >= HH || ww < 0 || ww >= WWD) continue;
        float4 v = *(const float4*)&Cin_[(hh*WWD + ww)*CO + cb];
        float ax = v.x*sc.x + sh.x; ax = (ax >= 0.f) ? ax : 0.01f*ax;
        float ay = v.y*sc.y + sh.y; ay = (ay >= 0.f) ? ay : 0.01f*ay;
        float az = v.z*sc.z + sh.z; az = (az >= 0.f) ? az : 0.01f*az;
        float aw = v.w*sc.w + sh.w; aw = (aw >= 0.f) ? aw : 0.01f*aw;
        acc.x += dws[(cb+0)*9+t] * ax;
        acc.y += dws[(cb+1)*9+t] * ay;
        acc.z += dws[(cb+2)*9+t] * az;
        acc.w += dws[(cb+3)*9+t] * aw;
    }
    union { __nv_bfloat162 b2[2]; uint2 u; } hv, lv;
    split_bf16(acc.x, hv.b2[0].x, lv.b2[0].x);
    split_bf16(acc.y, hv.b2[0].y, lv.b2[0].y);
    split_bf16(acc.z, hv.b2[1].x, lv.b2[1].x);
    split_bf16(acc.w, hv.b2[1].y, lv.b2[1].y);
    *(uint2*)&Zh[p*CO + cb] = hv.u;
    *(uint2*)&Zl[p*CO + cb] = lv.u;
}

// ---------------- 7) final act + transpose to NCHW ----------------
__global__ void k_final(float* __restrict__ out) {
    __shared__ float s[32][33];
    int ptile = blockIdx.x * 32;
    int ctile = blockIdx.y * 32;
    int tx = threadIdx.x, ty = threadIdx.y;  // 32 x 8
    #pragma unroll
    for (int i = 0; i < 32; i += 8) {
        int p = ptile + ty + i, c = ctile + tx;
        float v = g_C3[p*CO + c];
        float a = v*g_bn[2*2*CO + c] + g_bn[2*2*CO + CO + c];
        a = (a >= 0.f) ? a : 0.01f*a;
        s[ty+i][tx] = a;
    }
    __syncthreads();
    #pragma unroll
    for (int i = 0; i < 32; i += 8)
        out[(ctile + ty + i)*HWX + ptile + tx] = s[tx][ty+i];
}

// ---------------- launch ----------------
extern "C" void kernel_launch(void* const* d_in, const int* in_sizes, int n_in,
                              void* d_out, int out_size) {
    const float* x        = (const float*)d_in[0];
    const float* x_range  = (const float*)d_in[1];
    const float* range_o  = (const float*)d_in[2];
    const float* w_reduce = (const float*)d_in[3];
    const float* g_r      = (const float*)d_in[4];
    const float* b_r      = (const float*)d_in[5];
    const float* dw1      = (const float*)d_in[6];
    const float* pw1      = (const float*)d_in[7];
    const float* g1       = (const float*)d_in[8];
    const float* b1       = (const float*)d_in[9];
    const float* dw2      = (const float*)d_in[10];
    const float* pw2      = (const float*)d_in[11];
    const float* g2       = (const float*)d_in[12];
    const float* b2       = (const float*)d_in[13];
    float* out = (float*)d_out;

    float *C1, *C2, *C3;
    __nv_bfloat16 *y1, *y2, *w1h, *w1l, *w2h, *w2l, *w3h, *w3l, *z1h, *z1l, *z2h, *z2l;
    cudaGetSymbolAddress((void**)&C1, g_C1);
    cudaGetSymbolAddress((void**)&C2, g_C2);
    cudaGetSymbolAddress((void**)&C3, g_C3);
    cudaGetSymbolAddress((void**)&y1, g_y1);
    cudaGetSymbolAddress((void**)&y2, g_y2);
    cudaGetSymbolAddress((void**)&w1h, g_w1h);
    cudaGetSymbolAddress((void**)&w1l, g_w1l);
    cudaGetSymbolAddress((void**)&w2h, g_w2h);
    cudaGetSymbolAddress((void**)&w2l, g_w2l);
    cudaGetSymbolAddress((void**)&w3h, g_w3h);
    cudaGetSymbolAddress((void**)&w3l, g_w3l);
    cudaGetSymbolAddress((void**)&z1h, g_z1h);
    cudaGetSymbolAddress((void**)&z1l, g_z1l);
    cudaGetSymbolAddress((void**)&z2h, g_z2h);
    cudaGetSymbolAddress((void**)&z2l, g_z2l);

    k_pad_transpose<<<dim3((PP+31)/32, CIN/32), dim3(32,8)>>>(x);
    k_weights<<<(HWX+255)/256, 256>>>(x_range);
    k_wsplit_all<<<265, 256>>>(w_reduce, pw1, pw2, range_o);
    k_gather<<<HWX/8, 256>>>();

    k_gemm_tc<<<NGB, 256>>>(y1, y2, w1h, w1l, C1, CIN);
    k_bn_final<<<CO, 128>>>(g_r, b_r, 0);
    k_dw<<<HWX/8, 256>>>(C1, dw1, z1h, z1l, 0);

    k_gemm_tc<<<NGB, 256>>>(z1h, z1l, w2h, w2l, C2, CO);
    k_bn_final<<<CO, 128>>>(g1, b1, 1);
    k_dw<<<HWX/8, 256>>>(C2, dw2, z2h, z2l, 1);

    k_gemm_tc<<<NGB, 256>>>(z2h, z2l, w3h, w3l, C3, CO);
    k_bn_final<<<CO, 128>>>(g2, b2, 2);

    k_final<<<dim3(HWX/32, CO/32), dim3(32,8)>>>(out);
}